// round 2
// baseline (speedup 1.0000x reference)
#include <cuda_runtime.h>
#include <math.h>

#define BB 2
#define SS 2048
#define HH 16
#define DM 1024
#define DH 192
#define NQKV 9216
#define DL 3072
#define BHN 32
#define MROWS 4096

// Scratch (device globals: no allocation allowed)
__device__ float g_h[MROWS * DH];                 // 3 MB
__device__ float g_q[BHN * DH * SS];              // 50 MB, layout [bh][d][s]
__device__ float g_k[BHN * DH * SS];
__device__ float g_v[BHN * DH * SS];
__device__ float g_attn[MROWS * DL];              // 50 MB, layout [b*S+s][h*192+d]

// ---------------------------------------------------------------------------
// Kernel 1: h = rmsnorm(x @ w_down) * rms_w      [4096,1024]@[1024,192]
// One block = 16 rows, 192 threads (one per output column).
// ---------------------------------------------------------------------------
__global__ void k_down_rms(const float* __restrict__ x,
                           const float* __restrict__ w_down,
                           const float* __restrict__ rms_w) {
    extern __shared__ float sm[];
    float* xs  = sm;                  // 16*1024
    float* red = sm + 16 * 1024;      // 16*192
    float* rs  = red + 16 * 192;      // 16

    int t  = threadIdx.x;             // 0..191
    int m0 = blockIdx.x * 16;

    const float4* xin = (const float4*)(x + (size_t)m0 * DM);
    float4* xs4 = (float4*)xs;
    for (int i = t; i < 16 * DM / 4; i += 192) xs4[i] = xin[i];
    __syncthreads();

    float acc[16];
#pragma unroll
    for (int r = 0; r < 16; r++) acc[r] = 0.f;

    for (int k = 0; k < DM; k += 4) {
        float w0 = w_down[(k + 0) * DH + t];
        float w1 = w_down[(k + 1) * DH + t];
        float w2 = w_down[(k + 2) * DH + t];
        float w3 = w_down[(k + 3) * DH + t];
#pragma unroll
        for (int r = 0; r < 16; r++) {
            float4 xv = *(const float4*)&xs[r * DM + k];
            acc[r] += xv.x * w0 + xv.y * w1 + xv.z * w2 + xv.w * w3;
        }
    }

#pragma unroll
    for (int r = 0; r < 16; r++) red[r * 192 + t] = acc[r] * acc[r];
    __syncthreads();
    for (int st = 96; st >= 3; st >>= 1) {
        if (t < st) {
#pragma unroll
            for (int r = 0; r < 16; r++) red[r * 192 + t] += red[r * 192 + t + st];
        }
        __syncthreads();
    }
    if (t < 16) {
        float s3 = red[t * 192 + 0] + red[t * 192 + 1] + red[t * 192 + 2];
        rs[t] = rsqrtf(s3 / 192.0f + 1e-6f);
    }
    __syncthreads();

    float w = rms_w[t];
#pragma unroll
    for (int r = 0; r < 16; r++)
        g_h[(size_t)(m0 + r) * DH + t] = acc[r] * rs[r] * w;
}

// ---------------------------------------------------------------------------
// Kernel 2: qkv = h @ w_up, scattered into g_q/g_k/g_v [bh][d][s] layout.
// Tile 64(m) x 64(n), K=192 full. 256 threads, 4x4 microtile.
// tx -> m quad (writes coalesced along s), ty -> n quad.
// ---------------------------------------------------------------------------
__global__ void k_qkv(const float* __restrict__ w_up) {
    extern __shared__ float sm[];
    float* As = sm;                    // 192 * 68
    float* Bs = sm + 192 * 68;         // 192 * 64

    int tid = threadIdx.x;
    int tx = tid & 15, ty = tid >> 4;
    int m0 = blockIdx.x * 64;
    int n0 = blockIdx.y * 64;

    for (int i = tid; i < 64 * 192; i += 256) {
        int m = i / 192, k = i % 192;
        As[k * 68 + m] = g_h[(size_t)(m0 + m) * DH + k];
    }
    for (int i = tid; i < 192 * 64; i += 256) {
        int k = i >> 6, n = i & 63;
        Bs[k * 64 + n] = w_up[(size_t)k * NQKV + n0 + n];
    }
    __syncthreads();

    float acc[4][4];                   // [j(n)][i(m)]
#pragma unroll
    for (int j = 0; j < 4; j++)
#pragma unroll
        for (int i = 0; i < 4; i++) acc[j][i] = 0.f;

#pragma unroll 4
    for (int k = 0; k < 192; k++) {
        float4 a = *(const float4*)&As[k * 68 + tx * 4];
        float4 b = *(const float4*)&Bs[k * 64 + ty * 4];
        acc[0][0] += b.x * a.x; acc[0][1] += b.x * a.y; acc[0][2] += b.x * a.z; acc[0][3] += b.x * a.w;
        acc[1][0] += b.y * a.x; acc[1][1] += b.y * a.y; acc[1][2] += b.y * a.z; acc[1][3] += b.y * a.w;
        acc[2][0] += b.z * a.x; acc[2][1] += b.z * a.y; acc[2][2] += b.z * a.z; acc[2][3] += b.z * a.w;
        acc[3][0] += b.w * a.x; acc[3][1] += b.w * a.y; acc[3][2] += b.w * a.z; acc[3][3] += b.w * a.w;
    }

    int b_ = m0 >> 11;
    int s0 = m0 & 2047;
#pragma unroll
    for (int j = 0; j < 4; j++) {
        int n = n0 + ty * 4 + j;
        int ten = n / 3072;
        int l = n % 3072;
        int h_ = l & 15;
        int d  = l >> 4;
        float* dst = (ten == 0) ? g_q : ((ten == 1) ? g_k : g_v);
        float4 v4 = make_float4(acc[j][0], acc[j][1], acc[j][2], acc[j][3]);
        *(float4*)&dst[((size_t)(b_ * HH + h_) * DH + d) * SS + s0 + tx * 4] = v4;
    }
}

// ---------------------------------------------------------------------------
// Kernel 3: partial RoPE on q and k (first 32 of the 64 rope dims).
// grid (S/256, 16 pairs, 64 = {q,k} x 32 bh)
// ---------------------------------------------------------------------------
__global__ void k_rope() {
    int s = blockIdx.x * 256 + threadIdx.x;
    int p = blockIdx.y;                  // pair 0..15
    int z = blockIdx.z;                  // 0..63
    float* t = (z < 32) ? g_q : g_k;
    int bh = z & 31;

    float inv = (float)exp(-(double)(2 * p) / 32.0 * 9.210340371976184); // ln(10000)
    float ang = (float)s * inv;
    float c = cosf(ang), sn = sinf(ang);

    size_t i1 = ((size_t)bh * DH + 128 + 2 * p) * SS + s;
    size_t i2 = i1 + SS;
    float x1 = t[i1], x2 = t[i2];
    t[i1] = x1 * c - x2 * sn;
    t[i2] = x2 * c + x1 * sn;
}

// ---------------------------------------------------------------------------
// Kernel 4: causal flash attention per (bh, 64-query tile).
// Q/K tiles [192][64], V tile [192][65], P [64][68] (i-major).
// Threads (tx,ty)=16x16: scores i=ty*4, j=tx*4; PV i=ty*4, d=tx*12.
// ---------------------------------------------------------------------------
__global__ void __launch_bounds__(256, 1) k_attn() {
    extern __shared__ float sm[];
    float* Qs   = sm;                    // 192*64 = 12288
    float* Ks   = Qs + 12288;            // 12288
    float* Vs   = Ks + 12288;            // 192*65 = 12480
    float* Ps   = Vs + 12480;            // 64*68 = 4352
    float* rowm = Ps + 4352;             // 64
    float* rowl = rowm + 64;             // 64
    float* rowc = rowl + 64;             // 64

    int tid = threadIdx.x;
    int tx = tid & 15, ty = tid >> 4;
    int lane = tid & 31, warp = tid >> 5;

    int bh = blockIdx.y;
    int it = (gridDim.x - 1) - blockIdx.x;   // longest tiles scheduled first
    int i0 = it * 64;

    const float* qg = g_q + (size_t)bh * DH * SS;
    const float* kg = g_k + (size_t)bh * DH * SS;
    const float* vg = g_v + (size_t)bh * DH * SS;

    for (int idx = tid; idx < 192 * 16; idx += 256) {
        int k = idx >> 4, iv = idx & 15;
        *(float4*)&Qs[k * 64 + iv * 4] = *(const float4*)&qg[(size_t)k * SS + i0 + iv * 4];
    }
    if (tid < 64) { rowm[tid] = -1e30f; rowl[tid] = 0.f; }

    float o[4][12];
#pragma unroll
    for (int i = 0; i < 4; i++)
#pragma unroll
        for (int d = 0; d < 12; d++) o[i][d] = 0.f;

    const float scale = 0.07216878364870323f;   // 1/sqrt(192)

    for (int j0 = 0; j0 <= i0; j0 += 64) {
        __syncthreads();
        for (int idx = tid; idx < 192 * 16; idx += 256) {
            int k = idx >> 4, jv = idx & 15;
            *(float4*)&Ks[k * 64 + jv * 4] = *(const float4*)&kg[(size_t)k * SS + j0 + jv * 4];
        }
        for (int idx = tid; idx < 192 * 64; idx += 256) {
            int d = idx >> 6, j = idx & 63;
            Vs[d * 65 + j] = vg[(size_t)d * SS + j0 + j];
        }
        __syncthreads();

        // S = Q^T K  (i = ty*4+ii, j = tx*4+jj)
        float sc[4][4];
#pragma unroll
        for (int ii = 0; ii < 4; ii++)
#pragma unroll
            for (int jj = 0; jj < 4; jj++) sc[ii][jj] = 0.f;

#pragma unroll 4
        for (int k = 0; k < 192; k++) {
            float4 q  = *(const float4*)&Qs[k * 64 + ty * 4];
            float4 kv = *(const float4*)&Ks[k * 64 + tx * 4];
            sc[0][0] += q.x * kv.x; sc[0][1] += q.x * kv.y; sc[0][2] += q.x * kv.z; sc[0][3] += q.x * kv.w;
            sc[1][0] += q.y * kv.x; sc[1][1] += q.y * kv.y; sc[1][2] += q.y * kv.z; sc[1][3] += q.y * kv.w;
            sc[2][0] += q.z * kv.x; sc[2][1] += q.z * kv.y; sc[2][2] += q.z * kv.z; sc[2][3] += q.z * kv.w;
            sc[3][0] += q.w * kv.x; sc[3][1] += q.w * kv.y; sc[3][2] += q.w * kv.z; sc[3][3] += q.w * kv.w;
        }

#pragma unroll
        for (int ii = 0; ii < 4; ii++) {
            int gi = i0 + ty * 4 + ii;
            float4 v4;
            float* pv = (float*)&v4;
#pragma unroll
            for (int jj = 0; jj < 4; jj++) {
                float val = sc[ii][jj] * scale;
                if (j0 + tx * 4 + jj > gi) val = -1e9f;
                pv[jj] = val;
            }
            *(float4*)&Ps[(ty * 4 + ii) * 68 + tx * 4] = v4;
        }
        __syncthreads();

        // online softmax row stats: warp handles 8 rows
        for (int rr = 0; rr < 8; rr++) {
            int i = warp * 8 + rr;
            float v0 = Ps[i * 68 + lane];
            float v1 = Ps[i * 68 + 32 + lane];
            float mx = fmaxf(v0, v1);
#pragma unroll
            for (int off = 16; off > 0; off >>= 1)
                mx = fmaxf(mx, __shfl_xor_sync(0xffffffffu, mx, off));
            float oldm = rowm[i];
            float nm = fmaxf(oldm, mx);
            float e0 = __expf(v0 - nm);
            float e1 = __expf(v1 - nm);
            Ps[i * 68 + lane] = e0;
            Ps[i * 68 + 32 + lane] = e1;
            float sme = e0 + e1;
#pragma unroll
            for (int off = 16; off > 0; off >>= 1)
                sme += __shfl_xor_sync(0xffffffffu, sme, off);
            if (lane == 0) {
                float c = __expf(oldm - nm);
                rowc[i] = c;
                rowl[i] = rowl[i] * c + sme;
                rowm[i] = nm;
            }
        }
        __syncthreads();

        // rescale O, then O += P @ V^T   (i = ty*4+ii, d = tx*12+dd)
#pragma unroll
        for (int ii = 0; ii < 4; ii++) {
            float c = rowc[ty * 4 + ii];
#pragma unroll
            for (int dd = 0; dd < 12; dd++) o[ii][dd] *= c;
        }
#pragma unroll 2
        for (int j = 0; j < 64; j++) {
            float p0 = Ps[(ty * 4 + 0) * 68 + j];
            float p1 = Ps[(ty * 4 + 1) * 68 + j];
            float p2 = Ps[(ty * 4 + 2) * 68 + j];
            float p3 = Ps[(ty * 4 + 3) * 68 + j];
            float vv[12];
#pragma unroll
            for (int dd = 0; dd < 12; dd++) vv[dd] = Vs[(tx * 12 + dd) * 65 + j];
#pragma unroll
            for (int dd = 0; dd < 12; dd++) {
                o[0][dd] += p0 * vv[dd];
                o[1][dd] += p1 * vv[dd];
                o[2][dd] += p2 * vv[dd];
                o[3][dd] += p3 * vv[dd];
            }
        }
    }

    int b_ = bh >> 4;
    int h_ = bh & 15;
#pragma unroll
    for (int ii = 0; ii < 4; ii++) {
        int i = ty * 4 + ii;
        float inv = 1.f / rowl[i];
        float* dst = g_attn + (size_t)(b_ * SS + i0 + i) * DL + h_ * DH + tx * 12;
#pragma unroll
        for (int dd = 0; dd < 12; dd++) dst[dd] = o[ii][dd] * inv;
    }
}

// ---------------------------------------------------------------------------
// Kernel 5: out = g_attn @ w_o    [4096,3072]@[3072,1024]
// Tile 64x64, TK=32, 256 threads, 4x4 microtile. tx -> n (coalesced writes).
// ---------------------------------------------------------------------------
__global__ void k_out(const float* __restrict__ w_o, float* __restrict__ out) {
    __shared__ float As[32 * 65];
    __shared__ float Bs[32 * 64];

    int tid = threadIdx.x;
    int tx = tid & 15, ty = tid >> 4;
    int m0 = blockIdx.x * 64;
    int n0 = blockIdx.y * 64;

    float acc[4][4];                  // [ii(m)][jj(n)]
#pragma unroll
    for (int i = 0; i < 4; i++)
#pragma unroll
        for (int j = 0; j < 4; j++) acc[i][j] = 0.f;

    for (int k0 = 0; k0 < DL; k0 += 32) {
        __syncthreads();
        for (int i = tid; i < 64 * 32; i += 256) {
            int m = i >> 5, kk = i & 31;
            As[kk * 65 + m] = g_attn[(size_t)(m0 + m) * DL + k0 + kk];
        }
        for (int i = tid; i < 32 * 64; i += 256) {
            int kk = i >> 6, n = i & 63;
            Bs[kk * 64 + n] = w_o[(size_t)(k0 + kk) * DM + n0 + n];
        }
        __syncthreads();

#pragma unroll 8
        for (int kk = 0; kk < 32; kk++) {
            float a0 = As[kk * 65 + ty * 4 + 0];
            float a1 = As[kk * 65 + ty * 4 + 1];
            float a2 = As[kk * 65 + ty * 4 + 2];
            float a3 = As[kk * 65 + ty * 4 + 3];
            float4 b = *(const float4*)&Bs[kk * 64 + tx * 4];
            acc[0][0] += a0 * b.x; acc[0][1] += a0 * b.y; acc[0][2] += a0 * b.z; acc[0][3] += a0 * b.w;
            acc[1][0] += a1 * b.x; acc[1][1] += a1 * b.y; acc[1][2] += a1 * b.z; acc[1][3] += a1 * b.w;
            acc[2][0] += a2 * b.x; acc[2][1] += a2 * b.y; acc[2][2] += a2 * b.z; acc[2][3] += a2 * b.w;
            acc[3][0] += a3 * b.x; acc[3][1] += a3 * b.y; acc[3][2] += a3 * b.z; acc[3][3] += a3 * b.w;
        }
    }

#pragma unroll
    for (int ii = 0; ii < 4; ii++) {
        float4 v4 = make_float4(acc[ii][0], acc[ii][1], acc[ii][2], acc[ii][3]);
        *(float4*)&out[(size_t)(m0 + ty * 4 + ii) * DM + n0 + tx * 4] = v4;
    }
}

// ---------------------------------------------------------------------------
extern "C" void kernel_launch(void* const* d_in, const int* in_sizes, int n_in,
                              void* d_out, int out_size) {
    (void)in_sizes; (void)n_in; (void)out_size;
    const float* x      = (const float*)d_in[0];
    // d_in[1] = mask (int32 tril) — causality applied analytically, ignored
    const float* w_down = (const float*)d_in[2];
    const float* rms_w  = (const float*)d_in[3];
    const float* w_up   = (const float*)d_in[4];
    const float* w_o    = (const float*)d_in[5];
    float* out = (float*)d_out;

    cudaFuncSetAttribute(k_down_rms, cudaFuncAttributeMaxDynamicSharedMemorySize, 77888);
    cudaFuncSetAttribute(k_qkv,      cudaFuncAttributeMaxDynamicSharedMemorySize, 101376);
    cudaFuncSetAttribute(k_attn,     cudaFuncAttributeMaxDynamicSharedMemorySize, 166400);

    k_down_rms<<<256, 192, 77888>>>(x, w_down, rms_w);
    k_qkv<<<dim3(64, 144), 256, 101376>>>(w_up);
    k_rope<<<dim3(8, 16, 64), 256>>>();
    k_attn<<<dim3(32, 32), 256, 166400>>>();
    k_out<<<dim3(64, 16), 256>>>(w_o, out);
}

// round 3
// speedup vs baseline: 1.4242x; 1.4242x over previous
#include <cuda_runtime.h>
#include <math.h>

#define SS 2048
#define HH 16
#define DM 1024
#define DH 192
#define NQKV 9216
#define DL 3072
#define BHN 32
#define MROWS 4096

// Scratch (device globals: no allocation allowed)
__device__ float g_h[MROWS * DH];                 // 3 MB
__device__ float g_q[BHN * DH * SS];              // 50 MB, layout [bh][d][s]
__device__ float g_k[BHN * DH * SS];
__device__ float g_v[BHN * DH * SS];
__device__ float g_attn[MROWS * DL];              // 50 MB, layout [b*S+s][h*192+d]

// ---------------------------------------------------------------------------
// tf32 helpers (mma.sync m16n8k8, row.col, f32 accumulate)
// ---------------------------------------------------------------------------
__device__ __forceinline__ unsigned f2tf(float f) {
    unsigned u;
    asm("cvt.rna.tf32.f32 %0, %1;" : "=r"(u) : "f"(f));
    return u;
}

__device__ __forceinline__ void mma8(float4& d, const uint4& a, const uint2& b) {
    asm volatile("mma.sync.aligned.m16n8k8.row.col.f32.tf32.tf32.f32 "
                 "{%0,%1,%2,%3}, {%4,%5,%6,%7}, {%8,%9}, {%0,%1,%2,%3};\n"
                 : "+f"(d.x), "+f"(d.y), "+f"(d.z), "+f"(d.w)
                 : "r"(a.x), "r"(a.y), "r"(a.z), "r"(a.w), "r"(b.x), "r"(b.y));
}

// Fragment-order SMEM layouts (tf32 bits stored as unsigned):
//  A (16x8 per frag): elem (m,k) -> [ks=k>>3][mslab=m>>4][lane=(m&7)*4+(k&3)][reg=((k&7)>=4)*2+((m&15)>=8)]
//  B (8k x 8n):       elem (k,n) -> [ks=k>>3][nslab=n>>3][lane=(n&7)*4+(k&3)][reg=((k&7)>=4)]
//  Then in the hot loop lane L loads its own fragment directly: A=uint4 at
//  [ks][mslab][L][0..3], B=uint2 at [ks][nslab][L][0..1].

// ---------------------------------------------------------------------------
// Kernel 1: h = rmsnorm(x @ w_down) * rms_w      [4096,1024]@[1024,192]
// ---------------------------------------------------------------------------
__global__ void k_down_rms(const float* __restrict__ x,
                           const float* __restrict__ w_down,
                           const float* __restrict__ rms_w) {
    extern __shared__ float sm[];
    float* xs  = sm;                  // 16*1024
    float* red = sm + 16 * 1024;      // 16*192
    float* rs  = red + 16 * 192;      // 16

    int t  = threadIdx.x;             // 0..191
    int m0 = blockIdx.x * 16;

    const float4* xin = (const float4*)(x + (size_t)m0 * DM);
    float4* xs4 = (float4*)xs;
    for (int i = t; i < 16 * DM / 4; i += 192) xs4[i] = xin[i];
    __syncthreads();

    float acc[16];
#pragma unroll
    for (int r = 0; r < 16; r++) acc[r] = 0.f;

    for (int k = 0; k < DM; k += 4) {
        float w0 = w_down[(k + 0) * DH + t];
        float w1 = w_down[(k + 1) * DH + t];
        float w2 = w_down[(k + 2) * DH + t];
        float w3 = w_down[(k + 3) * DH + t];
#pragma unroll
        for (int r = 0; r < 16; r++) {
            float4 xv = *(const float4*)&xs[r * DM + k];
            acc[r] += xv.x * w0 + xv.y * w1 + xv.z * w2 + xv.w * w3;
        }
    }

#pragma unroll
    for (int r = 0; r < 16; r++) red[r * 192 + t] = acc[r] * acc[r];
    __syncthreads();
    for (int st = 96; st >= 3; st >>= 1) {
        if (t < st) {
#pragma unroll
            for (int r = 0; r < 16; r++) red[r * 192 + t] += red[r * 192 + t + st];
        }
        __syncthreads();
    }
    if (t < 16) {
        float s3 = red[t * 192 + 0] + red[t * 192 + 1] + red[t * 192 + 2];
        rs[t] = rsqrtf(s3 / 192.0f + 1e-6f);
    }
    __syncthreads();

    float w = rms_w[t];
#pragma unroll
    for (int r = 0; r < 16; r++)
        g_h[(size_t)(m0 + r) * DH + t] = acc[r] * rs[r] * w;
}

// ---------------------------------------------------------------------------
// Kernel 2: qkv = h @ w_up (tf32 mma), scatter into g_q/g_k/g_v [bh][d][s].
// BM=64, BN=128, K=192. 256 threads = 8 warps as 2(m) x 4(n); warp = 32x32.
// ---------------------------------------------------------------------------
#define QKV_SMEM ((24 * 4 * 32 * 4 + 24 * 16 * 32 * 2) * 4)   // 147456 B
__global__ void __launch_bounds__(256, 1) k_qkv_mma(const float* __restrict__ w_up) {
    extern __shared__ unsigned smu[];
    unsigned* Af = smu;                         // [24][4][32][4]
    unsigned* Bf = smu + 24 * 4 * 32 * 4;       // [24][16][32][2]

    int tid = threadIdx.x;
    int lane = tid & 31, warp = tid >> 5;
    int wm = warp >> 2, wn = warp & 3;
    int m0 = blockIdx.x * 64;
    int n0 = blockIdx.y * 128;

    // A: 64x192 from g_h (row-major)
    for (int i = tid; i < 64 * 48; i += 256) {
        int m = i / 48, k = (i % 48) * 4;
        float4 v = *(const float4*)&g_h[(size_t)(m0 + m) * DH + k];
        int ks = k >> 3;
        int rb = (((k & 7) >= 4) ? 2 : 0) + (((m & 15) >= 8) ? 1 : 0);
        unsigned* dst = &Af[((ks * 4 + (m >> 4)) * 32 + (m & 7) * 4 + (k & 3)) * 4 + rb];
        dst[0] = f2tf(v.x); dst[4] = f2tf(v.y); dst[8] = f2tf(v.z); dst[12] = f2tf(v.w);
    }
    // B: 192x128 from w_up (row-major)
    for (int i = tid; i < 192 * 32; i += 256) {
        int k = i >> 5, n = (i & 31) * 4;
        float4 v = *(const float4*)&w_up[(size_t)k * NQKV + n0 + n];
        int ks = k >> 3;
        int rb = ((k & 7) >= 4) ? 1 : 0;
        unsigned* dst = &Bf[((ks * 16 + (n >> 3)) * 32 + (n & 7) * 4 + (k & 3)) * 2 + rb];
        dst[0] = f2tf(v.x); dst[8] = f2tf(v.y); dst[16] = f2tf(v.z); dst[24] = f2tf(v.w);
    }
    __syncthreads();

    float4 acc[2][4];
#pragma unroll
    for (int im = 0; im < 2; im++)
#pragma unroll
        for (int in = 0; in < 4; in++) acc[im][in] = make_float4(0.f, 0.f, 0.f, 0.f);

#pragma unroll
    for (int ks = 0; ks < 24; ks++) {
        uint4 a0 = *(const uint4*)&Af[((ks * 4 + wm * 2 + 0) * 32 + lane) * 4];
        uint4 a1 = *(const uint4*)&Af[((ks * 4 + wm * 2 + 1) * 32 + lane) * 4];
        uint2 b[4];
#pragma unroll
        for (int in = 0; in < 4; in++)
            b[in] = *(const uint2*)&Bf[((ks * 16 + wn * 4 + in) * 32 + lane) * 2];
#pragma unroll
        for (int in = 0; in < 4; in++) { mma8(acc[0][in], a0, b[in]); mma8(acc[1][in], a1, b[in]); }
    }

    int b_ = m0 >> 11;
    int s0 = m0 & 2047;
#pragma unroll
    for (int im = 0; im < 2; im++)
#pragma unroll
        for (int h = 0; h < 2; h++) {
            int m = wm * 32 + im * 16 + h * 8 + (lane >> 2);
            int s = s0 + m;
#pragma unroll
            for (int in = 0; in < 4; in++) {
                float v0 = h ? acc[im][in].z : acc[im][in].x;
                float v1 = h ? acc[im][in].w : acc[im][in].y;
#pragma unroll
                for (int cc = 0; cc < 2; cc++) {
                    int n = n0 + wn * 32 + in * 8 + 2 * (lane & 3) + cc;
                    int ten = n / 3072;
                    int l = n % 3072;
                    int h_ = l & 15, d = l >> 4;
                    float* dst = (ten == 0) ? g_q : ((ten == 1) ? g_k : g_v);
                    dst[((size_t)(b_ * HH + h_) * DH + d) * SS + s] = cc ? v1 : v0;
                }
            }
        }
}

// ---------------------------------------------------------------------------
// Kernel 3: partial RoPE on q and k (first 32 of the 64 rope dims).
// ---------------------------------------------------------------------------
__global__ void k_rope() {
    int s = blockIdx.x * 256 + threadIdx.x;
    int p = blockIdx.y;                  // pair 0..15
    int z = blockIdx.z;                  // 0..63
    float* t = (z < 32) ? g_q : g_k;
    int bh = z & 31;

    float inv = (float)exp(-(double)(2 * p) / 32.0 * 9.210340371976184); // ln(10000)
    float ang = (float)s * inv;
    float c = cosf(ang), sn = sinf(ang);

    size_t i1 = ((size_t)bh * DH + 128 + 2 * p) * SS + s;
    size_t i2 = i1 + SS;
    float x1 = t[i1], x2 = t[i2];
    t[i1] = x1 * c - x2 * sn;
    t[i2] = x2 * c + x1 * sn;
}

// ---------------------------------------------------------------------------
// Kernel 4: causal flash attention with tf32 mma. Q tile 64 rows, full D=192.
// 256 threads = 8 warps. QK: warps 2(m)x4(n) -> warp 32x16 of S.
// PV:  warps 2(m)x4(n) over d -> warp 32x48 of O.
// SMEM (unsigned): Qf[24][4][32][4]  Kf[24][8][32][2]  Vf[8][24][32][2]
//                  Pf[8][4][32][4]   + float red arrays.
// ---------------------------------------------------------------------------
#define ATT_SMEM ((12288 * 3 + 4096) * 4 + 704 * 4)   // 166656 B
__global__ void __launch_bounds__(256, 1) k_attn_mma() {
    extern __shared__ unsigned smu[];
    unsigned* Qf = smu;                 // 12288
    unsigned* Kf = Qf + 12288;          // 12288
    unsigned* Vf = Kf + 12288;          // 12288
    unsigned* Pf = Vf + 12288;          // 4096
    float* redm = (float*)(Pf + 4096);  // [64][4]
    float* reds = redm + 256;           // [64][4]
    float* rowm = reds + 256;           // 64
    float* rowl = rowm + 64;            // 64
    float* rowc = rowl + 64;            // 64

    int tid = threadIdx.x, lane = tid & 31, warp = tid >> 5;
    int wm = warp >> 2, wn = warp & 3;
    int bh = blockIdx.y;
    int it = (gridDim.x - 1) - blockIdx.x;     // longest tiles first
    int i0 = it * 64;

    const float* qg = g_q + (size_t)bh * DH * SS;
    const float* kg = g_k + (size_t)bh * DH * SS;
    const float* vg = g_v + (size_t)bh * DH * SS;

    // Q tile: elem (i, d) = qg[d*SS + i0 + i], into A-frag layout (m=i, k=d)
    for (int idx = tid; idx < 192 * 16; idx += 256) {
        int d = idx >> 4, i = (idx & 15) * 4;
        float4 v = *(const float4*)&qg[(size_t)d * SS + i0 + i];
        int ks = d >> 3;
        int rb = (((d & 7) >= 4) ? 2 : 0) + (((i & 15) >= 8) ? 1 : 0);
        unsigned* dst = &Qf[((ks * 4 + (i >> 4)) * 32 + (i & 7) * 4 + (d & 3)) * 4 + rb];
        dst[0] = f2tf(v.x); dst[16] = f2tf(v.y); dst[32] = f2tf(v.z); dst[48] = f2tf(v.w);
    }
    if (tid < 64) { rowm[tid] = -3.0e38f; rowl[tid] = 0.f; }

    float4 o[2][6];
#pragma unroll
    for (int im = 0; im < 2; im++)
#pragma unroll
        for (int in = 0; in < 6; in++) o[im][in] = make_float4(0.f, 0.f, 0.f, 0.f);

    const float scale = 0.07216878364870323f;   // 1/sqrt(192)
    int ntile = it + 1;

    for (int jt = 0; jt < ntile; jt++) {
        int j0 = jt * 64;
        bool diag = (j0 == i0);
        __syncthreads();

        // K tile: (k=d, n=j) B-frag
        for (int idx = tid; idx < 192 * 16; idx += 256) {
            int d = idx >> 4, j = (idx & 15) * 4;
            float4 v = *(const float4*)&kg[(size_t)d * SS + j0 + j];
            int ks = d >> 3;
            int rb = ((d & 7) >= 4) ? 1 : 0;
            unsigned* dst = &Kf[((ks * 8 + (j >> 3)) * 32 + (j & 7) * 4 + (d & 3)) * 2 + rb];
            dst[0] = f2tf(v.x); dst[8] = f2tf(v.y); dst[16] = f2tf(v.z); dst[24] = f2tf(v.w);
        }
        // V tile: (k=j, n=d) B-frag
        for (int idx = tid; idx < 192 * 16; idx += 256) {
            int d = idx >> 4, j = (idx & 15) * 4;
            float4 v = *(const float4*)&vg[(size_t)d * SS + j0 + j];
            int ks = j >> 3;
            int rb = ((j & 7) >= 4) ? 1 : 0;
            unsigned* dst = &Vf[((ks * 24 + (d >> 3)) * 32 + (d & 7) * 4 + (j & 3)) * 2 + rb];
            dst[0] = f2tf(v.x); dst[2] = f2tf(v.y); dst[4] = f2tf(v.z); dst[6] = f2tf(v.w);
        }
        __syncthreads();

        // S = Q K^T : warp tile 32(m) x 16(n)
        float4 s[2][2];
#pragma unroll
        for (int im = 0; im < 2; im++)
#pragma unroll
            for (int in = 0; in < 2; in++) s[im][in] = make_float4(0.f, 0.f, 0.f, 0.f);

#pragma unroll
        for (int ks = 0; ks < 24; ks++) {
            uint4 a0 = *(const uint4*)&Qf[((ks * 4 + wm * 2 + 0) * 32 + lane) * 4];
            uint4 a1 = *(const uint4*)&Qf[((ks * 4 + wm * 2 + 1) * 32 + lane) * 4];
            uint2 b0 = *(const uint2*)&Kf[((ks * 8 + wn * 2 + 0) * 32 + lane) * 2];
            uint2 b1 = *(const uint2*)&Kf[((ks * 8 + wn * 2 + 1) * 32 + lane) * 2];
            mma8(s[0][0], a0, b0); mma8(s[0][1], a0, b1);
            mma8(s[1][0], a1, b0); mma8(s[1][1], a1, b1);
        }

        // scale + mask + per-row tile max (quad shuffle, then cross-warp smem)
        float pvv[2][2][2][2];
#pragma unroll
        for (int im = 0; im < 2; im++)
#pragma unroll
            for (int h = 0; h < 2; h++) {
                int row = wm * 32 + im * 16 + h * 8 + (lane >> 2);
                float mx = -3.0e38f;
#pragma unroll
                for (int in = 0; in < 2; in++) {
                    float v0 = (h ? s[im][in].z : s[im][in].x) * scale;
                    float v1 = (h ? s[im][in].w : s[im][in].y) * scale;
                    int col = wn * 16 + in * 8 + 2 * (lane & 3);
                    if (diag) {
                        if (col > row) v0 = -1e9f;
                        if (col + 1 > row) v1 = -1e9f;
                    }
                    pvv[im][h][in][0] = v0; pvv[im][h][in][1] = v1;
                    mx = fmaxf(mx, fmaxf(v0, v1));
                }
                mx = fmaxf(mx, __shfl_xor_sync(0xffffffffu, mx, 1));
                mx = fmaxf(mx, __shfl_xor_sync(0xffffffffu, mx, 2));
                if ((lane & 3) == 0) redm[row * 4 + wn] = mx;
            }
        __syncthreads();

        // exp, partial sums, and P -> A-frag layout in SMEM
#pragma unroll
        for (int im = 0; im < 2; im++)
#pragma unroll
            for (int h = 0; h < 2; h++) {
                int row = wm * 32 + im * 16 + h * 8 + (lane >> 2);
                float4 rp = *(const float4*)&redm[row * 4];
                float mn = fmaxf(fmaxf(fmaxf(rp.x, rp.y), fmaxf(rp.z, rp.w)), rowm[row]);
                float ssum = 0.f;
#pragma unroll
                for (int in = 0; in < 2; in++)
#pragma unroll
                    for (int cc = 0; cc < 2; cc++) {
                        float e = __expf(pvv[im][h][in][cc] - mn);
                        ssum += e;
                        int col = wn * 16 + in * 8 + 2 * (lane & 3) + cc;
                        int rb = (((lane & 3) >= 2) ? 2 : 0) + h;
                        int lt = (lane >> 2) * 4 + (col & 3);
                        Pf[(((col >> 3) * 4 + wm * 2 + im) * 32 + lt) * 4 + rb] = f2tf(e);
                    }
                ssum += __shfl_xor_sync(0xffffffffu, ssum, 1);
                ssum += __shfl_xor_sync(0xffffffffu, ssum, 2);
                if ((lane & 3) == 0) reds[row * 4 + wn] = ssum;
            }
        __syncthreads();

        // canonical row-state update
        if (tid < 64) {
            int row = tid;
            float4 rp = *(const float4*)&redm[row * 4];
            float tm = fmaxf(fmaxf(rp.x, rp.y), fmaxf(rp.z, rp.w));
            float mo = rowm[row];
            float mn = fmaxf(mo, tm);
            float4 sp = *(const float4*)&reds[row * 4];
            float ts = sp.x + sp.y + sp.z + sp.w;
            float c = __expf(mo - mn);
            rowc[row] = c;
            rowl[row] = rowl[row] * c + ts;
            rowm[row] = mn;
        }
        __syncthreads();

        // rescale O, then O += P @ V (warp tile 32(m) x 48(d))
        float cf0[2], cf1[2];
#pragma unroll
        for (int im = 0; im < 2; im++) {
            cf0[im] = rowc[wm * 32 + im * 16 + 0 + (lane >> 2)];
            cf1[im] = rowc[wm * 32 + im * 16 + 8 + (lane >> 2)];
        }
#pragma unroll
        for (int im = 0; im < 2; im++)
#pragma unroll
            for (int in = 0; in < 6; in++) {
                o[im][in].x *= cf0[im]; o[im][in].y *= cf0[im];
                o[im][in].z *= cf1[im]; o[im][in].w *= cf1[im];
            }
#pragma unroll
        for (int ks = 0; ks < 8; ks++) {
            uint4 a0 = *(const uint4*)&Pf[((ks * 4 + wm * 2 + 0) * 32 + lane) * 4];
            uint4 a1 = *(const uint4*)&Pf[((ks * 4 + wm * 2 + 1) * 32 + lane) * 4];
            uint2 b[6];
#pragma unroll
            for (int in = 0; in < 6; in++)
                b[in] = *(const uint2*)&Vf[((ks * 24 + wn * 6 + in) * 32 + lane) * 2];
#pragma unroll
            for (int in = 0; in < 6; in++) { mma8(o[0][in], a0, b[in]); mma8(o[1][in], a1, b[in]); }
        }
    }

    // epilogue: normalize and store to g_attn [b*S+s][h*192+d]
    int b_ = bh >> 4;
    int h_ = bh & 15;
#pragma unroll
    for (int im = 0; im < 2; im++)
#pragma unroll
        for (int h = 0; h < 2; h++) {
            int row = wm * 32 + im * 16 + h * 8 + (lane >> 2);
            float inv = 1.f / rowl[row];
            float* dst = &g_attn[(size_t)(b_ * SS + i0 + row) * DL + h_ * DH];
#pragma unroll
            for (int in = 0; in < 6; in++) {
                int d = wn * 48 + in * 8 + 2 * (lane & 3);
                float2 v;
                v.x = (h ? o[im][in].z : o[im][in].x) * inv;
                v.y = (h ? o[im][in].w : o[im][in].y) * inv;
                *(float2*)&dst[d] = v;
            }
        }
}

// ---------------------------------------------------------------------------
// Kernel 5: out = g_attn @ w_o  (tf32 mma)  [4096,3072]@[3072,1024]
// BM=64, BN=128, BK=48. 256 threads = 8 warps as 2(m) x 4(n); warp 32x32.
// ---------------------------------------------------------------------------
__global__ void __launch_bounds__(256, 1) k_out_mma(const float* __restrict__ w_o,
                                                    float* __restrict__ out) {
    __shared__ unsigned Af[6 * 4 * 32 * 4];    // 3072
    __shared__ unsigned Bf[6 * 16 * 32 * 2];   // 6144

    int tid = threadIdx.x, lane = tid & 31, warp = tid >> 5;
    int wm = warp >> 2, wn = warp & 3;
    int m0 = blockIdx.x * 64;
    int n0 = blockIdx.y * 128;

    float4 acc[2][4];
#pragma unroll
    for (int im = 0; im < 2; im++)
#pragma unroll
        for (int in = 0; in < 4; in++) acc[im][in] = make_float4(0.f, 0.f, 0.f, 0.f);

    for (int kc = 0; kc < DL; kc += 48) {
        __syncthreads();
        // A: 64 x 48 from g_attn
        for (int i = tid; i < 64 * 12; i += 256) {
            int m = i / 12, k = (i % 12) * 4;
            float4 v = *(const float4*)&g_attn[(size_t)(m0 + m) * DL + kc + k];
            int ks = k >> 3;
            int rb = (((k & 7) >= 4) ? 2 : 0) + (((m & 15) >= 8) ? 1 : 0);
            unsigned* dst = &Af[((ks * 4 + (m >> 4)) * 32 + (m & 7) * 4 + (k & 3)) * 4 + rb];
            dst[0] = f2tf(v.x); dst[4] = f2tf(v.y); dst[8] = f2tf(v.z); dst[12] = f2tf(v.w);
        }
        // B: 48 x 128 from w_o
        for (int i = tid; i < 48 * 32; i += 256) {
            int k = i >> 5, n = (i & 31) * 4;
            float4 v = *(const float4*)&w_o[(size_t)(kc + k) * DM + n0 + n];
            int ks = k >> 3;
            int rb = ((k & 7) >= 4) ? 1 : 0;
            unsigned* dst = &Bf[((ks * 16 + (n >> 3)) * 32 + (n & 7) * 4 + (k & 3)) * 2 + rb];
            dst[0] = f2tf(v.x); dst[8] = f2tf(v.y); dst[16] = f2tf(v.z); dst[24] = f2tf(v.w);
        }
        __syncthreads();

#pragma unroll
        for (int ks = 0; ks < 6; ks++) {
            uint4 a0 = *(const uint4*)&Af[((ks * 4 + wm * 2 + 0) * 32 + lane) * 4];
            uint4 a1 = *(const uint4*)&Af[((ks * 4 + wm * 2 + 1) * 32 + lane) * 4];
            uint2 b[4];
#pragma unroll
            for (int in = 0; in < 4; in++)
                b[in] = *(const uint2*)&Bf[((ks * 16 + wn * 4 + in) * 32 + lane) * 2];
#pragma unroll
            for (int in = 0; in < 4; in++) { mma8(acc[0][in], a0, b[in]); mma8(acc[1][in], a1, b[in]); }
        }
    }

#pragma unroll
    for (int im = 0; im < 2; im++)
#pragma unroll
        for (int h = 0; h < 2; h++) {
            int m = m0 + wm * 32 + im * 16 + h * 8 + (lane >> 2);
#pragma unroll
            for (int in = 0; in < 4; in++) {
                int n = n0 + wn * 32 + in * 8 + 2 * (lane & 3);
                float2 v;
                v.x = h ? acc[im][in].z : acc[im][in].x;
                v.y = h ? acc[im][in].w : acc[im][in].y;
                *(float2*)&out[(size_t)m * DM + n] = v;
            }
        }
}

// ---------------------------------------------------------------------------
extern "C" void kernel_launch(void* const* d_in, const int* in_sizes, int n_in,
                              void* d_out, int out_size) {
    (void)in_sizes; (void)n_in; (void)out_size;
    const float* x      = (const float*)d_in[0];
    // d_in[1] = mask (int32 tril) — causality applied analytically, ignored
    const float* w_down = (const float*)d_in[2];
    const float* rms_w  = (const float*)d_in[3];
    const float* w_up   = (const float*)d_in[4];
    const float* w_o    = (const float*)d_in[5];
    float* out = (float*)d_out;

    cudaFuncSetAttribute(k_down_rms, cudaFuncAttributeMaxDynamicSharedMemorySize, 77888);
    cudaFuncSetAttribute(k_qkv_mma,  cudaFuncAttributeMaxDynamicSharedMemorySize, QKV_SMEM);
    cudaFuncSetAttribute(k_attn_mma, cudaFuncAttributeMaxDynamicSharedMemorySize, ATT_SMEM);

    k_down_rms<<<256, 192, 77888>>>(x, w_down, rms_w);
    k_qkv_mma<<<dim3(64, 72), 256, QKV_SMEM>>>(w_up);
    k_rope<<<dim3(8, 16, 64), 256>>>();
    k_attn_mma<<<dim3(32, 32), 256, ATT_SMEM>>>();
    k_out_mma<<<dim3(64, 8), 256>>>(w_o, out);
}

// round 5
// speedup vs baseline: 3.7314x; 2.6199x over previous
#include <cuda_runtime.h>
#include <cuda_fp16.h>
#include <math.h>

#define SS 2048
#define HH 16
#define DM 1024
#define DH 192
#define NQKV 9216
#define DL 3072
#define BHN 32
#define MROWS 4096

// Scratch (device globals: no allocation allowed)
__device__ float  g_h[MROWS * DH];                // 3 MB fp32
__device__ __half g_q[BHN * DH * SS];             // 25 MB, layout [bh][d][s]
__device__ __half g_k[BHN * DH * SS];
__device__ __half g_v[BHN * DH * SS];
__device__ __half g_attn[MROWS * DL];             // 25 MB, layout [b*S+s][h*192+d]

// ---------------------------------------------------------------------------
// f16 mma helpers (mma.sync m16n8k16, row.col, f32 accumulate)
// Fragment-order SMEM layouts (elements are half2 pairs along k, as unsigned):
//  A (16x16): (m,kp) -> [ks=k>>4][ms=m>>4][lane=(m&7)*4+(kp&3)][reg=((k&15)>=8)*2+((m&15)>=8)]
//  B (16x8):  (kp,n) -> [ks][ns=n>>3][lane=(n&7)*4+(kp&3)][reg=((k&15)>=8)]
//  Physical lane is XOR-swizzled by slab: SW(lane, slab) — loads stay
//  conflict-free (per-slab constant permutation), fills spread banks.
// ---------------------------------------------------------------------------
#define SW(l, s) ((l) ^ (((s) & 3) << 2))

__device__ __forceinline__ unsigned pack2(float a, float b) {
    __half2 h = __floats2half2_rn(a, b);
    return *(unsigned*)&h;
}

__device__ __forceinline__ void mma16(float4& d, const uint4& a, const uint2& b) {
    asm volatile("mma.sync.aligned.m16n8k16.row.col.f32.f16.f16.f32 "
                 "{%0,%1,%2,%3}, {%4,%5,%6,%7}, {%8,%9}, {%0,%1,%2,%3};\n"
                 : "+f"(d.x), "+f"(d.y), "+f"(d.z), "+f"(d.w)
                 : "r"(a.x), "r"(a.y), "r"(a.z), "r"(a.w), "r"(b.x), "r"(b.y));
}

// ---------------------------------------------------------------------------
// Kernel 1: h = rmsnorm(x @ w_down) * rms_w      [4096,1024]@[1024,192]
// ---------------------------------------------------------------------------
__global__ void k_down_rms(const float* __restrict__ x,
                           const float* __restrict__ w_down,
                           const float* __restrict__ rms_w) {
    extern __shared__ float sm[];
    float* xs  = sm;                  // 16*1024
    float* red = sm + 16 * 1024;      // 16*192
    float* rs  = red + 16 * 192;      // 16

    int t  = threadIdx.x;             // 0..191
    int m0 = blockIdx.x * 16;

    const float4* xin = (const float4*)(x + (size_t)m0 * DM);
    float4* xs4 = (float4*)xs;
    for (int i = t; i < 16 * DM / 4; i += 192) xs4[i] = xin[i];
    __syncthreads();

    float acc[16];
#pragma unroll
    for (int r = 0; r < 16; r++) acc[r] = 0.f;

    for (int k = 0; k < DM; k += 4) {
        float w0 = w_down[(k + 0) * DH + t];
        float w1 = w_down[(k + 1) * DH + t];
        float w2 = w_down[(k + 2) * DH + t];
        float w3 = w_down[(k + 3) * DH + t];
#pragma unroll
        for (int r = 0; r < 16; r++) {
            float4 xv = *(const float4*)&xs[r * DM + k];
            acc[r] += xv.x * w0 + xv.y * w1 + xv.z * w2 + xv.w * w3;
        }
    }

#pragma unroll
    for (int r = 0; r < 16; r++) red[r * 192 + t] = acc[r] * acc[r];
    __syncthreads();
    for (int st = 96; st >= 3; st >>= 1) {
        if (t < st) {
#pragma unroll
            for (int r = 0; r < 16; r++) red[r * 192 + t] += red[r * 192 + t + st];
        }
        __syncthreads();
    }
    if (t < 16) {
        float s3 = red[t * 192 + 0] + red[t * 192 + 1] + red[t * 192 + 2];
        rs[t] = rsqrtf(s3 / 192.0f + 1e-6f);
    }
    __syncthreads();

    float w = rms_w[t];
#pragma unroll
    for (int r = 0; r < 16; r++)
        g_h[(size_t)(m0 + r) * DH + t] = acc[r] * rs[r] * w;
}

// ---------------------------------------------------------------------------
// Kernel 2: qkv = h @ w_up (f16 mma), scatter into g_q/g_k/g_v [bh][d][s].
// BM=64, BN=128, K=192. 8 warps = 2(m) x 4(n); warp tile 32x32.
// ---------------------------------------------------------------------------
#define QKV_SMEM ((12 * 4 * 128 + 12 * 16 * 64) * 4)   // 73728 B
__global__ void __launch_bounds__(256, 2) k_qkv_mma(const float* __restrict__ w_up) {
    extern __shared__ unsigned smu[];
    unsigned* Af = smu;                   // [12][4][128]
    unsigned* Bf = smu + 12 * 4 * 128;    // [12][16][64]

    int tid = threadIdx.x, lane = tid & 31, warp = tid >> 5;
    int wm = warp >> 2, wn = warp & 3;
    int m0 = blockIdx.x * 64;
    int n0 = blockIdx.y * 128;

    // A: 64x192 fp32 rows of g_h -> half2 pairs along k
    for (int i = tid; i < 64 * 48; i += 256) {
        int m = i / 48, k4 = (i % 48) * 4;
        float4 v = *(const float4*)&g_h[(size_t)(m0 + m) * DH + k4];
        int ks = k4 >> 4, ms = m >> 4;
        int reg = (((k4 & 15) >= 8) ? 2 : 0) + (((m & 15) >= 8) ? 1 : 0);
        int l0 = (m & 7) * 4 + ((k4 >> 1) & 3);
        unsigned* base = &Af[(ks * 4 + ms) * 128];
        base[SW(l0, ms) * 4 + reg]     = pack2(v.x, v.y);
        base[SW(l0 + 1, ms) * 4 + reg] = pack2(v.z, v.w);
    }
    // B: 192x128 fp32 rows of w_up -> pairs along k from two rows
    for (int i = tid; i < 96 * 32; i += 256) {
        int kp = i >> 5, n4 = (i & 31) * 4;
        int k = kp * 2;
        const float* p = &w_up[(size_t)k * NQKV + n0 + n4];
        float4 r0 = *(const float4*)p;
        float4 r1 = *(const float4*)(p + NQKV);
        int ks = k >> 4, reg = ((k & 15) >= 8) ? 1 : 0;
        int c = (k & 7) >> 1;
        float a0[4] = {r0.x, r0.y, r0.z, r0.w};
        float a1[4] = {r1.x, r1.y, r1.z, r1.w};
#pragma unroll
        for (int j = 0; j < 4; j++) {
            int n = n4 + j, ns = n >> 3;
            int l = (n & 7) * 4 + c;
            Bf[(ks * 16 + ns) * 64 + SW(l, ns) * 2 + reg] = pack2(a0[j], a1[j]);
        }
    }
    __syncthreads();

    float4 acc[2][4];
#pragma unroll
    for (int im = 0; im < 2; im++)
#pragma unroll
        for (int in = 0; in < 4; in++) acc[im][in] = make_float4(0.f, 0.f, 0.f, 0.f);

#pragma unroll
    for (int ks = 0; ks < 12; ks++) {
        uint4 a0 = *(const uint4*)&Af[(ks * 4 + wm * 2 + 0) * 128 + SW(lane, wm * 2) * 4];
        uint4 a1 = *(const uint4*)&Af[(ks * 4 + wm * 2 + 1) * 128 + SW(lane, wm * 2 + 1) * 4];
        uint2 b[4];
#pragma unroll
        for (int in = 0; in < 4; in++) {
            int ns = wn * 4 + in;
            b[in] = *(const uint2*)&Bf[(ks * 16 + ns) * 64 + SW(lane, ns) * 2];
        }
#pragma unroll
        for (int in = 0; in < 4; in++) { mma16(acc[0][in], a0, b[in]); mma16(acc[1][in], a1, b[in]); }
    }

    int b_ = m0 >> 11;
    int s0 = m0 & 2047;
#pragma unroll
    for (int im = 0; im < 2; im++)
#pragma unroll
        for (int h = 0; h < 2; h++) {
            int m = wm * 32 + im * 16 + h * 8 + (lane >> 2);
            int s = s0 + m;
#pragma unroll
            for (int in = 0; in < 4; in++) {
                float v0 = h ? acc[im][in].z : acc[im][in].x;
                float v1 = h ? acc[im][in].w : acc[im][in].y;
#pragma unroll
                for (int cc = 0; cc < 2; cc++) {
                    int n = n0 + wn * 32 + in * 8 + 2 * (lane & 3) + cc;
                    int ten = n / 3072;
                    int l = n % 3072;
                    int h_ = l & 15, d = l >> 4;
                    __half* dst = (ten == 0) ? g_q : ((ten == 1) ? g_k : g_v);
                    dst[((size_t)(b_ * HH + h_) * DH + d) * SS + s] = __float2half(cc ? v1 : v0);
                }
            }
        }
}

// ---------------------------------------------------------------------------
// Kernel 3: partial RoPE on q and k (fp16 in-place, 2 s-positions per thread).
// ---------------------------------------------------------------------------
__global__ void k_rope() {
    int s = (blockIdx.x * 256 + threadIdx.x) * 2;
    int p = blockIdx.y;                  // pair 0..15
    int z = blockIdx.z;                  // 0..63
    __half* t = (z < 32) ? g_q : g_k;
    int bh = z & 31;

    float inv = (float)exp(-(double)(2 * p) / 32.0 * 9.210340371976184); // ln(10000)
    float a0 = (float)s * inv, a1 = (float)(s + 1) * inv;
    float c0 = cosf(a0), s_0 = sinf(a0);
    float c1 = cosf(a1), s_1 = sinf(a1);

    size_t i1 = ((size_t)bh * DH + 128 + 2 * p) * SS + s;
    size_t i2 = i1 + SS;
    float2 x1 = __half22float2(*(__half2*)&t[i1]);
    float2 x2 = __half22float2(*(__half2*)&t[i2]);
    *(__half2*)&t[i1] = __floats2half2_rn(x1.x * c0 - x2.x * s_0, x1.y * c1 - x2.y * s_1);
    *(__half2*)&t[i2] = __floats2half2_rn(x2.x * c0 + x1.x * s_0, x2.y * c1 + x1.y * s_1);
}

// ---------------------------------------------------------------------------
// Kernel 4: causal flash attention with f16 mma. Q tile 64 rows, D=192.
// 8 warps: QK 2(m)x4(n) -> warp 32x16 of S; PV 2(m)x4(n over d) -> warp 32x48.
// SMEM: Qf[12][4][128] Kf[12][8][64] Vf[4][24][64] Pf[4][4][128] + reductions.
// ---------------------------------------------------------------------------
#define ATT_SMEM ((6144 * 3 + 2048) * 4 + 704 * 4)   // 84736 B
__global__ void __launch_bounds__(256, 2) k_attn_mma() {
    extern __shared__ unsigned smu[];
    unsigned* Qf = smu;                 // 6144
    unsigned* Kf = Qf + 6144;           // 6144
    unsigned* Vf = Kf + 6144;           // 6144
    unsigned* Pf = Vf + 6144;           // 2048
    float* redm = (float*)(Pf + 2048);  // [64][4]
    float* reds = redm + 256;           // [64][4]
    float* rowm = reds + 256;           // 64
    float* rowl = rowm + 64;            // 64
    float* rowc = rowl + 64;            // 64

    int tid = threadIdx.x, lane = tid & 31, warp = tid >> 5;
    int wm = warp >> 2, wn = warp & 3;
    int bh = blockIdx.y;
    int it = (gridDim.x - 1) - blockIdx.x;     // longest tiles first
    int i0 = it * 64;

    const __half* qg = g_q + (size_t)bh * DH * SS;
    const __half* kg = g_k + (size_t)bh * DH * SS;
    const __half* vg = g_v + (size_t)bh * DH * SS;

    // Q tile -> A-frag (m=i, k=d). Pairs along d from two rows.
    for (int idx = tid; idx < 96 * 16; idx += 256) {
        int dp = idx >> 4, ig = idx & 15;
        int d = dp * 2, i4 = ig * 4;
        const __half* p = qg + (size_t)d * SS + i0 + i4;
        uint2 q0 = *(const uint2*)p;
        uint2 q1 = *(const uint2*)(p + SS);
        __half2 a0 = *(__half2*)&q0.x, a1 = *(__half2*)&q0.y;
        __half2 b0 = *(__half2*)&q1.x, b1 = *(__half2*)&q1.y;
        __half2 u[4] = { __lows2half2(a0, b0), __highs2half2(a0, b0),
                         __lows2half2(a1, b1), __highs2half2(a1, b1) };
        int ks = d >> 4, c = (d & 7) >> 1;
        int regd = ((d & 15) >= 8) ? 2 : 0;
#pragma unroll
        for (int j = 0; j < 4; j++) {
            int i = i4 + j, ms = i >> 4;
            int reg = regd + (((i & 15) >= 8) ? 1 : 0);
            int l = (i & 7) * 4 + c;
            Qf[(ks * 4 + ms) * 128 + SW(l, ms) * 4 + reg] = *(unsigned*)&u[j];
        }
    }
    if (tid < 64) { rowm[tid] = -3.0e38f; rowl[tid] = 0.f; }

    float4 o[2][6];
#pragma unroll
    for (int im = 0; im < 2; im++)
#pragma unroll
        for (int in = 0; in < 6; in++) o[im][in] = make_float4(0.f, 0.f, 0.f, 0.f);

    const float scale = 0.07216878364870323f;   // 1/sqrt(192)
    int ntile = it + 1;

    for (int jt = 0; jt < ntile; jt++) {
        int j0 = jt * 64;
        bool diag = (j0 == i0);
        __syncthreads();

        // K tile -> B-frag (k=d, n=j)
        for (int idx = tid; idx < 96 * 16; idx += 256) {
            int dp = idx >> 4, jg = idx & 15;
            int d = dp * 2, j4 = jg * 4;
            const __half* p = kg + (size_t)d * SS + j0 + j4;
            uint2 q0 = *(const uint2*)p;
            uint2 q1 = *(const uint2*)(p + SS);
            __half2 a0 = *(__half2*)&q0.x, a1 = *(__half2*)&q0.y;
            __half2 b0 = *(__half2*)&q1.x, b1 = *(__half2*)&q1.y;
            __half2 u[4] = { __lows2half2(a0, b0), __highs2half2(a0, b0),
                             __lows2half2(a1, b1), __highs2half2(a1, b1) };
            int ks = d >> 4, c = (d & 7) >> 1;
            int reg = ((d & 15) >= 8) ? 1 : 0;
#pragma unroll
            for (int j = 0; j < 4; j++) {
                int jj = j4 + j, ns = jj >> 3;
                int l = (jj & 7) * 4 + c;
                Kf[(ks * 8 + ns) * 64 + SW(l, ns) * 2 + reg] = *(unsigned*)&u[j];
            }
        }
        // V tile -> B-frag (k=j, n=d). Pairs along j are native in [d][s].
        for (int idx = tid; idx < 192 * 16; idx += 256) {
            int d = idx >> 4, j4 = (idx & 15) * 4;
            uint2 v = *(const uint2*)(vg + (size_t)d * SS + j0 + j4);
            int ks = j4 >> 4, ns = d >> 3;
            int reg = ((j4 & 15) >= 8) ? 1 : 0;
            int l0 = (d & 7) * 4 + ((j4 >> 1) & 3);
            unsigned* base = &Vf[(ks * 24 + ns) * 64];
            base[SW(l0, ns) * 2 + reg]     = v.x;
            base[SW(l0 + 1, ns) * 2 + reg] = v.y;
        }
        __syncthreads();

        // S = Q K^T : warp tile 32(m) x 16(n)
        float4 s[2][2];
#pragma unroll
        for (int im = 0; im < 2; im++)
#pragma unroll
            for (int in = 0; in < 2; in++) s[im][in] = make_float4(0.f, 0.f, 0.f, 0.f);

#pragma unroll
        for (int ks = 0; ks < 12; ks++) {
            uint4 a0 = *(const uint4*)&Qf[(ks * 4 + wm * 2 + 0) * 128 + SW(lane, wm * 2) * 4];
            uint4 a1 = *(const uint4*)&Qf[(ks * 4 + wm * 2 + 1) * 128 + SW(lane, wm * 2 + 1) * 4];
            uint2 b0 = *(const uint2*)&Kf[(ks * 8 + wn * 2 + 0) * 64 + SW(lane, wn * 2) * 2];
            uint2 b1 = *(const uint2*)&Kf[(ks * 8 + wn * 2 + 1) * 64 + SW(lane, wn * 2 + 1) * 2];
            mma16(s[0][0], a0, b0); mma16(s[0][1], a0, b1);
            mma16(s[1][0], a1, b0); mma16(s[1][1], a1, b1);
        }

        // scale + mask + per-row tile max
        float pvv[2][2][2][2];
#pragma unroll
        for (int im = 0; im < 2; im++)
#pragma unroll
            for (int h = 0; h < 2; h++) {
                int row = wm * 32 + im * 16 + h * 8 + (lane >> 2);
                float mx = -3.0e38f;
#pragma unroll
                for (int in = 0; in < 2; in++) {
                    float v0 = (h ? s[im][in].z : s[im][in].x) * scale;
                    float v1 = (h ? s[im][in].w : s[im][in].y) * scale;
                    int col = wn * 16 + in * 8 + 2 * (lane & 3);
                    if (diag) {
                        if (col > row) v0 = -1e9f;
                        if (col + 1 > row) v1 = -1e9f;
                    }
                    pvv[im][h][in][0] = v0; pvv[im][h][in][1] = v1;
                    mx = fmaxf(mx, fmaxf(v0, v1));
                }
                mx = fmaxf(mx, __shfl_xor_sync(0xffffffffu, mx, 1));
                mx = fmaxf(mx, __shfl_xor_sync(0xffffffffu, mx, 2));
                if ((lane & 3) == 0) redm[row * 4 + wn] = mx;
            }
        __syncthreads();

        // exp + partial sums + P -> A-frag (m=row, k=col); lane_p == lane
#pragma unroll
        for (int im = 0; im < 2; im++)
#pragma unroll
            for (int h = 0; h < 2; h++) {
                int row = wm * 32 + im * 16 + h * 8 + (lane >> 2);
                float4 rp = *(const float4*)&redm[row * 4];
                float mn = fmaxf(fmaxf(fmaxf(rp.x, rp.y), fmaxf(rp.z, rp.w)), rowm[row]);
                float ssum = 0.f;
                int ms = wm * 2 + im;
#pragma unroll
                for (int in = 0; in < 2; in++) {
                    float e0 = __expf(pvv[im][h][in][0] - mn);
                    float e1 = __expf(pvv[im][h][in][1] - mn);
                    ssum += e0 + e1;
                    Pf[(wn * 4 + ms) * 128 + SW(lane, ms) * 4 + (in * 2 + h)] = pack2(e0, e1);
                }
                ssum += __shfl_xor_sync(0xffffffffu, ssum, 1);
                ssum += __shfl_xor_sync(0xffffffffu, ssum, 2);
                if ((lane & 3) == 0) reds[row * 4 + wn] = ssum;
            }
        __syncthreads();

        // canonical row-state update
        if (tid < 64) {
            int row = tid;
            float4 rp = *(const float4*)&redm[row * 4];
            float tm = fmaxf(fmaxf(rp.x, rp.y), fmaxf(rp.z, rp.w));
            float mo = rowm[row];
            float mn = fmaxf(mo, tm);
            float4 sp = *(const float4*)&reds[row * 4];
            float ts = sp.x + sp.y + sp.z + sp.w;
            float c = __expf(mo - mn);
            rowc[row] = c;
            rowl[row] = rowl[row] * c + ts;
            rowm[row] = mn;
        }
        __syncthreads();

        // rescale O, then O += P @ V (warp tile 32(m) x 48(d))
        float cf0[2], cf1[2];
#pragma unroll
        for (int im = 0; im < 2; im++) {
            cf0[im] = rowc[wm * 32 + im * 16 + 0 + (lane >> 2)];
            cf1[im] = rowc[wm * 32 + im * 16 + 8 + (lane >> 2)];
        }
#pragma unroll
        for (int im = 0; im < 2; im++)
#pragma unroll
            for (int in = 0; in < 6; in++) {
                o[im][in].x *= cf0[im]; o[im][in].y *= cf0[im];
                o[im][in].z *= cf1[im]; o[im][in].w *= cf1[im];
            }
#pragma unroll
        for (int ks = 0; ks < 4; ks++) {
            uint4 a0 = *(const uint4*)&Pf[(ks * 4 + wm * 2 + 0) * 128 + SW(lane, wm * 2) * 4];
            uint4 a1 = *(const uint4*)&Pf[(ks * 4 + wm * 2 + 1) * 128 + SW(lane, wm * 2 + 1) * 4];
            uint2 b[6];
#pragma unroll
            for (int in = 0; in < 6; in++) {
                int ns = wn * 6 + in;
                b[in] = *(const uint2*)&Vf[(ks * 24 + ns) * 64 + SW(lane, ns) * 2];
            }
#pragma unroll
            for (int in = 0; in < 6; in++) { mma16(o[0][in], a0, b[in]); mma16(o[1][in], a1, b[in]); }
        }
    }

    // epilogue: normalize, store half2 pairs to g_attn [b*S+s][h*192+d]
    int b_ = bh >> 4;
    int h_ = bh & 15;
#pragma unroll
    for (int im = 0; im < 2; im++)
#pragma unroll
        for (int h = 0; h < 2; h++) {
            int row = wm * 32 + im * 16 + h * 8 + (lane >> 2);
            float inv = 1.f / rowl[row];
            __half* dst = &g_attn[(size_t)(b_ * SS + i0 + row) * DL + h_ * DH];
#pragma unroll
            for (int in = 0; in < 6; in++) {
                int d = wn * 48 + in * 8 + 2 * (lane & 3);
                float vx = (h ? o[im][in].z : o[im][in].x) * inv;
                float vy = (h ? o[im][in].w : o[im][in].y) * inv;
                *(__half2*)&dst[d] = __floats2half2_rn(vx, vy);
            }
        }
}

// ---------------------------------------------------------------------------
// Kernel 5: out = g_attn @ w_o  (f16 mma)  [4096,3072]@[3072,1024]
// BM=64, BN=128, BK=64. 8 warps 2(m) x 4(n); warp 32x32.
// ---------------------------------------------------------------------------
__global__ void __launch_bounds__(256, 2) k_out_mma(const float* __restrict__ w_o,
                                                    float* __restrict__ out) {
    __shared__ unsigned Af[4 * 4 * 128];    // 8 KB
    __shared__ unsigned Bf[4 * 16 * 64];    // 16 KB

    int tid = threadIdx.x, lane = tid & 31, warp = tid >> 5;
    int wm = warp >> 2, wn = warp & 3;
    int m0 = blockIdx.x * 64;
    int n0 = blockIdx.y * 128;

    float4 acc[2][4];
#pragma unroll
    for (int im = 0; im < 2; im++)
#pragma unroll
        for (int in = 0; in < 4; in++) acc[im][in] = make_float4(0.f, 0.f, 0.f, 0.f);

    for (int kc = 0; kc < DL; kc += 64) {
        __syncthreads();
        // A: 64x64 halves of g_attn; k-pairs native
        for (int i = tid; i < 64 * 16; i += 256) {
            int m = i >> 4, k4 = (i & 15) * 4;
            uint2 v = *(const uint2*)&g_attn[(size_t)(m0 + m) * DL + kc + k4];
            int ks = k4 >> 4, ms = m >> 4;
            int reg = (((k4 & 15) >= 8) ? 2 : 0) + (((m & 15) >= 8) ? 1 : 0);
            int l0 = (m & 7) * 4 + ((k4 >> 1) & 3);
            unsigned* base = &Af[(ks * 4 + ms) * 128];
            base[SW(l0, ms) * 4 + reg]     = v.x;
            base[SW(l0 + 1, ms) * 4 + reg] = v.y;
        }
        // B: 64x128 fp32 rows of w_o; pairs along k from two rows
        for (int i = tid; i < 32 * 32; i += 256) {
            int kp = i >> 5, n4 = (i & 31) * 4;
            int k = kp * 2;
            const float* p = &w_o[(size_t)(kc + k) * DM + n0 + n4];
            float4 r0 = *(const float4*)p;
            float4 r1 = *(const float4*)(p + DM);
            int ks = k >> 4, reg = ((k & 15) >= 8) ? 1 : 0;
            int c = (k & 7) >> 1;
            float a0[4] = {r0.x, r0.y, r0.z, r0.w};
            float a1[4] = {r1.x, r1.y, r1.z, r1.w};
#pragma unroll
            for (int j = 0; j < 4; j++) {
                int n = n4 + j, ns = n >> 3;
                int l = (n & 7) * 4 + c;
                Bf[(ks * 16 + ns) * 64 + SW(l, ns) * 2 + reg] = pack2(a0[j], a1[j]);
            }
        }
        __syncthreads();

#pragma unroll
        for (int ks = 0; ks < 4; ks++) {
            uint4 a0 = *(const uint4*)&Af[(ks * 4 + wm * 2 + 0) * 128 + SW(lane, wm * 2) * 4];
            uint4 a1 = *(const uint4*)&Af[(ks * 4 + wm * 2 + 1) * 128 + SW(lane, wm * 2 + 1) * 4];
            uint2 b[4];
#pragma unroll
            for (int in = 0; in < 4; in++) {
                int ns = wn * 4 + in;
                b[in] = *(const uint2*)&Bf[(ks * 16 + ns) * 64 + SW(lane, ns) * 2];
            }
#pragma unroll
            for (int in = 0; in < 4; in++) { mma16(acc[0][in], a0, b[in]); mma16(acc[1][in], a1, b[in]); }
        }
    }

#pragma unroll
    for (int im = 0; im < 2; im++)
#pragma unroll
        for (int h = 0; h < 2; h++) {
            int m = m0 + wm * 32 + im * 16 + h * 8 + (lane >> 2);
#pragma unroll
            for (int in = 0; in < 4; in++) {
                int n = n0 + wn * 32 + in * 8 + 2 * (lane & 3);
                float2 v;
                v.x = h ? acc[im][in].z : acc[im][in].x;
                v.y = h ? acc[im][in].w : acc[im][in].y;
                *(float2*)&out[(size_t)m * DM + n] = v;
            }
        }
}

// ---------------------------------------------------------------------------
extern "C" void kernel_launch(void* const* d_in, const int* in_sizes, int n_in,
                              void* d_out, int out_size) {
    (void)in_sizes; (void)n_in; (void)out_size;
    const float* x      = (const float*)d_in[0];
    // d_in[1] = mask (int32 tril) — causality applied analytically, ignored
    const float* w_down = (const float*)d_in[2];
    const float* rms_w  = (const float*)d_in[3];
    const float* w_up   = (const float*)d_in[4];
    const float* w_o    = (const float*)d_in[5];
    float* out = (float*)d_out;

    cudaFuncSetAttribute(k_down_rms, cudaFuncAttributeMaxDynamicSharedMemorySize, 77888);
    cudaFuncSetAttribute(k_qkv_mma,  cudaFuncAttributeMaxDynamicSharedMemorySize, QKV_SMEM);
    cudaFuncSetAttribute(k_attn_mma, cudaFuncAttributeMaxDynamicSharedMemorySize, ATT_SMEM);

    k_down_rms<<<256, 192, 77888>>>(x, w_down, rms_w);
    k_qkv_mma<<<dim3(64, 72), 256, QKV_SMEM>>>(w_up);
    k_rope<<<dim3(4, 16, 64), 256>>>();
    k_attn_mma<<<dim3(32, 32), 256, ATT_SMEM>>>();
    k_out_mma<<<dim3(64, 8), 256>>>(w_o, out);
}

// round 6
// speedup vs baseline: 4.0482x; 1.0849x over previous
#include <cuda_runtime.h>
#include <cuda_fp16.h>
#include <math.h>

#define SS 2048
#define HH 16
#define DM 1024
#define DH 192
#define NQKV 9216
#define DL 3072
#define BHN 32
#define MROWS 4096

// Scratch (device globals: no allocation allowed)
__device__ float    g_h[MROWS * DH];              // 3 MB fp32
// Q in A-fragment tile layout: [bh][tile(32)][12ks][4ms][128]  (u32 = half2)
__device__ unsigned g_qf[BHN * 32 * 6144];        // 25 MB
// K in B-fragment tile layout: [bh][tile(32)][12ks][8ns][64]
__device__ unsigned g_kf[BHN * 32 * 6144];        // 25 MB
__device__ __half   g_v[BHN * DH * SS];           // 25 MB, layout [bh][d][s]
__device__ __half   g_attn[MROWS * DL];           // 25 MB, layout [b*S+s][h*192+d]

// ---------------------------------------------------------------------------
// f16 mma helpers (mma.sync m16n8k16, row.col, f32 accumulate)
//  A (16x16): (m,kp) -> [ks=k>>4][ms=m>>4][lane=(m&7)*4+(kp&3)][reg=((k&15)>=8)*2+((m&15)>=8)]
//  B (16x8):  (kp,n) -> [ks][ns=n>>3][lane=(n&7)*4+(kp&3)][reg=((k&15)>=8)]
//  Physical lane XOR-swizzled by slab: SW(lane, slab).
// ---------------------------------------------------------------------------
#define SW(l, s) ((l) ^ (((s) & 3) << 2))

__device__ __forceinline__ unsigned pack2(float a, float b) {
    __half2 h = __floats2half2_rn(a, b);
    return *(unsigned*)&h;
}

__device__ __forceinline__ void mma16(float4& d, const uint4& a, const uint2& b) {
    asm volatile("mma.sync.aligned.m16n8k16.row.col.f32.f16.f16.f32 "
                 "{%0,%1,%2,%3}, {%4,%5,%6,%7}, {%8,%9}, {%0,%1,%2,%3};\n"
                 : "+f"(d.x), "+f"(d.y), "+f"(d.z), "+f"(d.w)
                 : "r"(a.x), "r"(a.y), "r"(a.z), "r"(a.w), "r"(b.x), "r"(b.y));
}

// ---------------------------------------------------------------------------
// Kernel 1: h = rmsnorm(x @ w_down) * rms_w      [4096,1024]@[1024,192]
// ---------------------------------------------------------------------------
__global__ void k_down_rms(const float* __restrict__ x,
                           const float* __restrict__ w_down,
                           const float* __restrict__ rms_w) {
    extern __shared__ float sm[];
    float* xs  = sm;                  // 16*1024
    float* red = sm + 16 * 1024;      // 16*192
    float* rs  = red + 16 * 192;      // 16

    int t  = threadIdx.x;             // 0..191
    int m0 = blockIdx.x * 16;

    const float4* xin = (const float4*)(x + (size_t)m0 * DM);
    float4* xs4 = (float4*)xs;
    for (int i = t; i < 16 * DM / 4; i += 192) xs4[i] = xin[i];
    __syncthreads();

    float acc[16];
#pragma unroll
    for (int r = 0; r < 16; r++) acc[r] = 0.f;

    for (int k = 0; k < DM; k += 4) {
        float w0 = w_down[(k + 0) * DH + t];
        float w1 = w_down[(k + 1) * DH + t];
        float w2 = w_down[(k + 2) * DH + t];
        float w3 = w_down[(k + 3) * DH + t];
#pragma unroll
        for (int r = 0; r < 16; r++) {
            float4 xv = *(const float4*)&xs[r * DM + k];
            acc[r] += xv.x * w0 + xv.y * w1 + xv.z * w2 + xv.w * w3;
        }
    }

#pragma unroll
    for (int r = 0; r < 16; r++) red[r * 192 + t] = acc[r] * acc[r];
    __syncthreads();
    for (int st = 96; st >= 3; st >>= 1) {
        if (t < st) {
#pragma unroll
            for (int r = 0; r < 16; r++) red[r * 192 + t] += red[r * 192 + t + st];
        }
        __syncthreads();
    }
    if (t < 16) {
        float s3 = red[t * 192 + 0] + red[t * 192 + 1] + red[t * 192 + 2];
        rs[t] = rsqrtf(s3 / 192.0f + 1e-6f);
    }
    __syncthreads();

    float w = rms_w[t];
#pragma unroll
    for (int r = 0; r < 16; r++)
        g_h[(size_t)(m0 + r) * DH + t] = acc[r] * rs[r] * w;
}

// ---------------------------------------------------------------------------
// Kernel 2: qkv = h @ w_up (f16 mma). Q/K written directly in fragment-tile
// layout (half2 pair (d,d+1) = cols n and n+16 — both in-thread). V scattered
// to [bh][d][s]. BM=64, BN=128, K=192. 8 warps 2(m) x 4(n); warp 32x32.
// ---------------------------------------------------------------------------
#define QKV_SMEM ((12 * 4 * 128 + 12 * 16 * 64) * 4)   // 73728 B
__global__ void __launch_bounds__(256, 2) k_qkv_mma(const float* __restrict__ w_up) {
    extern __shared__ unsigned smu[];
    unsigned* Af = smu;                   // [12][4][128]
    unsigned* Bf = smu + 12 * 4 * 128;    // [12][16][64]

    int tid = threadIdx.x, lane = tid & 31, warp = tid >> 5;
    int wm = warp >> 2, wn = warp & 3;
    int m0 = blockIdx.x * 64;
    int n0 = blockIdx.y * 128;

    // A: 64x192 fp32 rows of g_h -> half2 pairs along k
    for (int i = tid; i < 64 * 48; i += 256) {
        int m = i / 48, k4 = (i % 48) * 4;
        float4 v = *(const float4*)&g_h[(size_t)(m0 + m) * DH + k4];
        int ks = k4 >> 4, ms = m >> 4;
        int reg = (((k4 & 15) >= 8) ? 2 : 0) + (((m & 15) >= 8) ? 1 : 0);
        int l0 = (m & 7) * 4 + ((k4 >> 1) & 3);
        unsigned* base = &Af[(ks * 4 + ms) * 128];
        base[SW(l0, ms) * 4 + reg]     = pack2(v.x, v.y);
        base[SW(l0 + 1, ms) * 4 + reg] = pack2(v.z, v.w);
    }
    // B: 192x128 fp32 rows of w_up -> pairs along k from two rows
    for (int i = tid; i < 96 * 32; i += 256) {
        int kp = i >> 5, n4 = (i & 31) * 4;
        int k = kp * 2;
        const float* p = &w_up[(size_t)k * NQKV + n0 + n4];
        float4 r0 = *(const float4*)p;
        float4 r1 = *(const float4*)(p + NQKV);
        int ks = k >> 4, reg = ((k & 15) >= 8) ? 1 : 0;
        int c = (k & 7) >> 1;
        float a0[4] = {r0.x, r0.y, r0.z, r0.w};
        float a1[4] = {r1.x, r1.y, r1.z, r1.w};
#pragma unroll
        for (int j = 0; j < 4; j++) {
            int n = n4 + j, ns = n >> 3;
            int l = (n & 7) * 4 + c;
            Bf[(ks * 16 + ns) * 64 + SW(l, ns) * 2 + reg] = pack2(a0[j], a1[j]);
        }
    }
    __syncthreads();

    float4 acc[2][4];
#pragma unroll
    for (int im = 0; im < 2; im++)
#pragma unroll
        for (int in = 0; in < 4; in++) acc[im][in] = make_float4(0.f, 0.f, 0.f, 0.f);

#pragma unroll
    for (int ks = 0; ks < 12; ks++) {
        uint4 a0 = *(const uint4*)&Af[(ks * 4 + wm * 2 + 0) * 128 + SW(lane, wm * 2) * 4];
        uint4 a1 = *(const uint4*)&Af[(ks * 4 + wm * 2 + 1) * 128 + SW(lane, wm * 2 + 1) * 4];
        uint2 b[4];
#pragma unroll
        for (int in = 0; in < 4; in++) {
            int ns = wn * 4 + in;
            b[in] = *(const uint2*)&Bf[(ks * 16 + ns) * 64 + SW(lane, ns) * 2];
        }
#pragma unroll
        for (int in = 0; in < 4; in++) { mma16(acc[0][in], a0, b[in]); mma16(acc[1][in], a1, b[in]); }
    }

    int b_ = m0 >> 11;
    int s0 = m0 & 2047;
    int ti = s0 >> 6;                        // 64-row tile index within bh
#pragma unroll
    for (int im = 0; im < 2; im++)
#pragma unroll
        for (int h = 0; h < 2; h++) {
            int m = wm * 32 + im * 16 + h * 8 + (lane >> 2);   // row in tile (0..63)
            int s = s0 + m;
#pragma unroll
            for (int in2 = 0; in2 < 2; in2++)
#pragma unroll
                for (int cc = 0; cc < 2; cc++) {
                    float vlo, vhi;
                    if (h) { vlo = cc ? acc[im][in2].w : acc[im][in2].z;
                             vhi = cc ? acc[im][in2 + 2].w : acc[im][in2 + 2].z; }
                    else   { vlo = cc ? acc[im][in2].y : acc[im][in2].x;
                             vhi = cc ? acc[im][in2 + 2].y : acc[im][in2 + 2].x; }
                    int n = n0 + wn * 32 + in2 * 8 + 2 * (lane & 3) + cc;
                    int ten = n / 3072;
                    int l = n % 3072;
                    int h_ = l & 15, d = l >> 4;     // d even; pair (d, d+1)
                    int bh = b_ * HH + h_;
                    if (ten == 2) {
                        g_v[((size_t)bh * DH + d) * SS + s]     = __float2half(vlo);
                        g_v[((size_t)bh * DH + d + 1) * SS + s] = __float2half(vhi);
                    } else {
                        unsigned w = pack2(vlo, vhi);
                        int ks = d >> 4, c = (d & 7) >> 1;
                        int lf = (m & 7) * 4 + c;
                        if (ten == 0) {      // Q: A-frag
                            int ms = m >> 4;
                            int reg = (((d & 15) >= 8) ? 2 : 0) + (((m & 15) >= 8) ? 1 : 0);
                            g_qf[(size_t)(bh * 32 + ti) * 6144 +
                                 (ks * 4 + ms) * 128 + SW(lf, ms) * 4 + reg] = w;
                        } else {             // K: B-frag
                            int ns = m >> 3;
                            int reg = ((d & 15) >= 8) ? 1 : 0;
                            g_kf[(size_t)(bh * 32 + ti) * 6144 +
                                 (ks * 8 + ns) * 64 + SW(lf, ns) * 2 + reg] = w;
                        }
                    }
                }
        }
}

// ---------------------------------------------------------------------------
// Kernel 3: partial RoPE on q and k, editing fragment-layout words in place.
// The rotation pair (d, d+1), d = 128+2p even, is exactly one half2 word.
// ---------------------------------------------------------------------------
__global__ void k_rope() {
    int s = blockIdx.x * 256 + threadIdx.x;     // 0..2047
    int p = blockIdx.y;                         // 0..15
    int z = blockIdx.z;                         // 0..63: <32 q, else k
    int bh = z & 31;
    int d = 128 + 2 * p;

    float inv = (float)exp(-(double)(2 * p) / 32.0 * 9.210340371976184); // ln(10000)
    float ang = (float)s * inv;
    float c = cosf(ang), sn = sinf(ang);

    int ti = s >> 6, m = s & 63;
    int ks = d >> 4, cf = (d & 7) >> 1;
    int lf = (m & 7) * 4 + cf;
    unsigned* base;
    int idx;
    if (z < 32) {     // Q A-frag
        int ms = m >> 4;
        int reg = (((d & 15) >= 8) ? 2 : 0) + (((m & 15) >= 8) ? 1 : 0);
        base = g_qf + (size_t)(bh * 32 + ti) * 6144;
        idx = (ks * 4 + ms) * 128 + SW(lf, ms) * 4 + reg;
    } else {          // K B-frag
        int ns = m >> 3;
        int reg = ((d & 15) >= 8) ? 1 : 0;
        base = g_kf + (size_t)(bh * 32 + ti) * 6144;
        idx = (ks * 8 + ns) * 64 + SW(lf, ns) * 2 + reg;
    }
    unsigned u = base[idx];
    float2 xv = __half22float2(*(__half2*)&u);
    base[idx] = pack2(xv.x * c - xv.y * sn, xv.y * c + xv.x * sn);
}

// ---------------------------------------------------------------------------
// Kernel 4: causal flash attention, Q fragments held in REGISTERS (invariant
// across the j-loop). K tile = raw uint4 copy of frag-layout gmem. 8 warps,
// 1 CTA/SM. SMEM: Kf[12][8][64] Vf[4][24][64] Pf[4][4][128] + reductions.
// ---------------------------------------------------------------------------
#define ATT_SMEM ((6144 * 2 + 2048 + 768) * 4)   // 60416 B
__global__ void __launch_bounds__(256, 1) k_attn_mma() {
    extern __shared__ unsigned smu[];
    unsigned* Kf = smu;                  // 6144
    unsigned* Vf = smu + 6144;           // 6144
    unsigned* Pf = smu + 12288;          // 2048
    float* redm = (float*)(smu + 14336); // [64][4]
    float* reds = redm + 256;            // [64][4]
    float* rowm = reds + 256;            // [2][64] parity double-buffer
    float* rowl = rowm + 128;            // [2][64]

    int tid = threadIdx.x, lane = tid & 31, warp = tid >> 5;
    int wm = warp >> 2, wn = warp & 3;
    int bh = blockIdx.y;
    int it = (gridDim.x - 1) - blockIdx.x;     // longest tiles first
    int i0 = it * 64;

    // Q fragments: 24 direct LDG.128 from frag-layout gmem, held for the CTA's life
    const unsigned* qt = g_qf + (size_t)(bh * 32 + it) * 6144;
    uint4 qreg[12][2];
#pragma unroll
    for (int ks = 0; ks < 12; ks++)
#pragma unroll
        for (int im = 0; im < 2; im++) {
            int ms = wm * 2 + im;
            qreg[ks][im] = *(const uint4*)&qt[(ks * 4 + ms) * 128 + SW(lane, ms) * 4];
        }

    if (tid < 64) { rowm[tid] = -3.0e38f; rowl[tid] = 0.f; }

    const __half* vg = g_v + (size_t)bh * DH * SS;

    float4 o[2][6];
#pragma unroll
    for (int im = 0; im < 2; im++)
#pragma unroll
        for (int in = 0; in < 6; in++) o[im][in] = make_float4(0.f, 0.f, 0.f, 0.f);

    const float scale = 0.07216878364870323f;   // 1/sqrt(192)
    int ntile = it + 1;

    for (int jt = 0; jt < ntile; jt++) {
        int j0 = jt * 64, par = jt & 1;
        bool diag = (jt == it);
        __syncthreads();                         // prev PV done / init done

        // K tile: raw copy of fragment-layout gmem (6 uint4 per thread)
        {
            const uint4* kt = (const uint4*)(g_kf + (size_t)(bh * 32 + jt) * 6144);
            uint4* kd = (uint4*)Kf;
#pragma unroll
            for (int i = 0; i < 6; i++) kd[tid + i * 256] = kt[tid + i * 256];
        }
        // V tile -> B-frag (k=j, n=d). Pairs along j are native in [d][s].
        for (int idx = tid; idx < 192 * 16; idx += 256) {
            int d = idx >> 4, j4 = (idx & 15) * 4;
            uint2 v = *(const uint2*)(vg + (size_t)d * SS + j0 + j4);
            int ks = j4 >> 4, ns = d >> 3;
            int reg = ((j4 & 15) >= 8) ? 1 : 0;
            int l0 = (d & 7) * 4 + ((j4 >> 1) & 3);
            unsigned* base = &Vf[(ks * 24 + ns) * 64];
            base[SW(l0, ns) * 2 + reg]     = v.x;
            base[SW(l0 + 1, ns) * 2 + reg] = v.y;
        }
        __syncthreads();

        // S = Q K^T : warp tile 32(m) x 16(n); A from registers, B from SMEM
        float4 s[2][2];
#pragma unroll
        for (int im = 0; im < 2; im++)
#pragma unroll
            for (int in = 0; in < 2; in++) s[im][in] = make_float4(0.f, 0.f, 0.f, 0.f);

#pragma unroll
        for (int ks = 0; ks < 12; ks++) {
            uint2 b0 = *(const uint2*)&Kf[(ks * 8 + wn * 2 + 0) * 64 + SW(lane, wn * 2) * 2];
            uint2 b1 = *(const uint2*)&Kf[(ks * 8 + wn * 2 + 1) * 64 + SW(lane, wn * 2 + 1) * 2];
            mma16(s[0][0], qreg[ks][0], b0); mma16(s[0][1], qreg[ks][0], b1);
            mma16(s[1][0], qreg[ks][1], b0); mma16(s[1][1], qreg[ks][1], b1);
        }

        // scale + mask + per-row tile max
        float pvv[2][2][2][2];
#pragma unroll
        for (int im = 0; im < 2; im++)
#pragma unroll
            for (int h = 0; h < 2; h++) {
                int row = wm * 32 + im * 16 + h * 8 + (lane >> 2);
                float mx = -3.0e38f;
#pragma unroll
                for (int in = 0; in < 2; in++) {
                    float v0 = (h ? s[im][in].z : s[im][in].x) * scale;
                    float v1 = (h ? s[im][in].w : s[im][in].y) * scale;
                    int col = wn * 16 + in * 8 + 2 * (lane & 3);
                    if (diag) {
                        if (col > row) v0 = -1e9f;
                        if (col + 1 > row) v1 = -1e9f;
                    }
                    pvv[im][h][in][0] = v0; pvv[im][h][in][1] = v1;
                    mx = fmaxf(mx, fmaxf(v0, v1));
                }
                mx = fmaxf(mx, __shfl_xor_sync(0xffffffffu, mx, 1));
                mx = fmaxf(mx, __shfl_xor_sync(0xffffffffu, mx, 2));
                if ((lane & 3) == 0) redm[row * 4 + wn] = mx;
            }
        __syncthreads();

        // exp + partial sums + P -> A-frag; new row-max to parity buffer
        float cloc[2][2];
#pragma unroll
        for (int im = 0; im < 2; im++)
#pragma unroll
            for (int h = 0; h < 2; h++) {
                int row = wm * 32 + im * 16 + h * 8 + (lane >> 2);
                float4 rp = *(const float4*)&redm[row * 4];
                float mo = rowm[par * 64 + row];
                float mn = fmaxf(fmaxf(fmaxf(rp.x, rp.y), fmaxf(rp.z, rp.w)), mo);
                cloc[im][h] = __expf(mo - mn);
                float ssum = 0.f;
                int ms = wm * 2 + im;
#pragma unroll
                for (int in = 0; in < 2; in++) {
                    float e0 = __expf(pvv[im][h][in][0] - mn);
                    float e1 = __expf(pvv[im][h][in][1] - mn);
                    ssum += e0 + e1;
                    Pf[(wn * 4 + ms) * 128 + SW(lane, ms) * 4 + (in * 2 + h)] = pack2(e0, e1);
                }
                ssum += __shfl_xor_sync(0xffffffffu, ssum, 1);
                ssum += __shfl_xor_sync(0xffffffffu, ssum, 2);
                if ((lane & 3) == 0) {
                    reds[row * 4 + wn] = ssum;
                    if (wn == 0) rowm[(par ^ 1) * 64 + row] = mn;
                }
            }
        __syncthreads();

        // distributed row-sum update (writers), rescale O, then O += P @ V
        if (wn == 0 && (lane & 3) == 0) {
#pragma unroll
            for (int im = 0; im < 2; im++)
#pragma unroll
                for (int h = 0; h < 2; h++) {
                    int row = wm * 32 + im * 16 + h * 8 + (lane >> 2);
                    float4 sp = *(const float4*)&reds[row * 4];
                    float ts = sp.x + sp.y + sp.z + sp.w;
                    rowl[(par ^ 1) * 64 + row] = rowl[par * 64 + row] * cloc[im][h] + ts;
                }
        }
#pragma unroll
        for (int im = 0; im < 2; im++)
#pragma unroll
            for (int in = 0; in < 6; in++) {
                o[im][in].x *= cloc[im][0]; o[im][in].y *= cloc[im][0];
                o[im][in].z *= cloc[im][1]; o[im][in].w *= cloc[im][1];
            }
#pragma unroll
        for (int ks = 0; ks < 4; ks++) {
            uint4 a0 = *(const uint4*)&Pf[(ks * 4 + wm * 2 + 0) * 128 + SW(lane, wm * 2) * 4];
            uint4 a1 = *(const uint4*)&Pf[(ks * 4 + wm * 2 + 1) * 128 + SW(lane, wm * 2 + 1) * 4];
            uint2 b[6];
#pragma unroll
            for (int in = 0; in < 6; in++) {
                int ns = wn * 6 + in;
                b[in] = *(const uint2*)&Vf[(ks * 24 + ns) * 64 + SW(lane, ns) * 2];
            }
#pragma unroll
            for (int in = 0; in < 6; in++) { mma16(o[0][in], a0, b[in]); mma16(o[1][in], a1, b[in]); }
        }
    }
    __syncthreads();                             // final rowl visible

    // epilogue: normalize, store half2 pairs to g_attn [b*S+s][h*192+d]
    int fpar = ntile & 1;
    int b_ = bh >> 4;
    int h_ = bh & 15;
#pragma unroll
    for (int im = 0; im < 2; im++)
#pragma unroll
        for (int h = 0; h < 2; h++) {
            int row = wm * 32 + im * 16 + h * 8 + (lane >> 2);
            float inv = 1.f / rowl[fpar * 64 + row];
            __half* dst = &g_attn[(size_t)(b_ * SS + i0 + row) * DL + h_ * DH];
#pragma unroll
            for (int in = 0; in < 6; in++) {
                int d = wn * 48 + in * 8 + 2 * (lane & 3);
                float vx = (h ? o[im][in].z : o[im][in].x) * inv;
                float vy = (h ? o[im][in].w : o[im][in].y) * inv;
                *(__half2*)&dst[d] = __floats2half2_rn(vx, vy);
            }
        }
}

// ---------------------------------------------------------------------------
// Kernel 5: out = g_attn @ w_o  (f16 mma)  [4096,3072]@[3072,1024]
// BM=128, BN=128, BK=64. 8 warps 4(m) x 2(n); warp 32x64.
// ---------------------------------------------------------------------------
#define OUT_SMEM ((4 * 8 * 128 + 4 * 16 * 64) * 4)   // 32768 B
__global__ void __launch_bounds__(256, 2) k_out_mma(const float* __restrict__ w_o,
                                                    float* __restrict__ out) {
    __shared__ unsigned Af[4 * 8 * 128];    // 16 KB
    __shared__ unsigned Bf[4 * 16 * 64];    // 16 KB

    int tid = threadIdx.x, lane = tid & 31, warp = tid >> 5;
    int wm = warp >> 1, wn = warp & 1;
    int m0 = blockIdx.x * 128;
    int n0 = blockIdx.y * 128;

    float4 acc[2][8];
#pragma unroll
    for (int im = 0; im < 2; im++)
#pragma unroll
        for (int in = 0; in < 8; in++) acc[im][in] = make_float4(0.f, 0.f, 0.f, 0.f);

    for (int kc = 0; kc < DL; kc += 64) {
        __syncthreads();
        // A: 128x64 halves of g_attn; k-pairs native
        for (int i = tid; i < 128 * 16; i += 256) {
            int m = i >> 4, k4 = (i & 15) * 4;
            uint2 v = *(const uint2*)&g_attn[(size_t)(m0 + m) * DL + kc + k4];
            int ks = k4 >> 4, ms = m >> 4;
            int reg = (((k4 & 15) >= 8) ? 2 : 0) + (((m & 15) >= 8) ? 1 : 0);
            int l0 = (m & 7) * 4 + ((k4 >> 1) & 3);
            unsigned* base = &Af[(ks * 8 + ms) * 128];
            base[SW(l0, ms) * 4 + reg]     = v.x;
            base[SW(l0 + 1, ms) * 4 + reg] = v.y;
        }
        // B: 64x128 fp32 rows of w_o; pairs along k from two rows
        for (int i = tid; i < 32 * 32; i += 256) {
            int kp = i >> 5, n4 = (i & 31) * 4;
            int k = kp * 2;
            const float* p = &w_o[(size_t)(kc + k) * DM + n0 + n4];
            float4 r0 = *(const float4*)p;
            float4 r1 = *(const float4*)(p + DM);
            int ks = k >> 4, reg = ((k & 15) >= 8) ? 1 : 0;
            int c = (k & 7) >> 1;
            float a0[4] = {r0.x, r0.y, r0.z, r0.w};
            float a1[4] = {r1.x, r1.y, r1.z, r1.w};
#pragma unroll
            for (int j = 0; j < 4; j++) {
                int n = n4 + j, ns = n >> 3;
                int l = (n & 7) * 4 + c;
                Bf[(ks * 16 + ns) * 64 + SW(l, ns) * 2 + reg] = pack2(a0[j], a1[j]);
            }
        }
        __syncthreads();

#pragma unroll
        for (int ks = 0; ks < 4; ks++) {
            uint4 a0 = *(const uint4*)&Af[(ks * 8 + wm * 2 + 0) * 128 + SW(lane, wm * 2) * 4];
            uint4 a1 = *(const uint4*)&Af[(ks * 8 + wm * 2 + 1) * 128 + SW(lane, wm * 2 + 1) * 4];
            uint2 b[8];
#pragma unroll
            for (int in = 0; in < 8; in++) {
                int ns = wn * 8 + in;
                b[in] = *(const uint2*)&Bf[(ks * 16 + ns) * 64 + SW(lane, ns) * 2];
            }
#pragma unroll
            for (int in = 0; in < 8; in++) { mma16(acc[0][in], a0, b[in]); mma16(acc[1][in], a1, b[in]); }
        }
    }

#pragma unroll
    for (int im = 0; im < 2; im++)
#pragma unroll
        for (int h = 0; h < 2; h++) {
            int m = m0 + wm * 32 + im * 16 + h * 8 + (lane >> 2);
#pragma unroll
            for (int in = 0; in < 8; in++) {
                int n = n0 + wn * 64 + in * 8 + 2 * (lane & 3);
                float2 v;
                v.x = h ? acc[im][in].z : acc[im][in].x;
                v.y = h ? acc[im][in].w : acc[im][in].y;
                *(float2*)&out[(size_t)m * DM + n] = v;
            }
        }
}

// ---------------------------------------------------------------------------
extern "C" void kernel_launch(void* const* d_in, const int* in_sizes, int n_in,
                              void* d_out, int out_size) {
    (void)in_sizes; (void)n_in; (void)out_size;
    const float* x      = (const float*)d_in[0];
    // d_in[1] = mask (int32 tril) — causality applied analytically, ignored
    const float* w_down = (const float*)d_in[2];
    const float* rms_w  = (const float*)d_in[3];
    const float* w_up   = (const float*)d_in[4];
    const float* w_o    = (const float*)d_in[5];
    float* out = (float*)d_out;

    cudaFuncSetAttribute(k_down_rms, cudaFuncAttributeMaxDynamicSharedMemorySize, 77888);
    cudaFuncSetAttribute(k_qkv_mma,  cudaFuncAttributeMaxDynamicSharedMemorySize, QKV_SMEM);
    cudaFuncSetAttribute(k_attn_mma, cudaFuncAttributeMaxDynamicSharedMemorySize, ATT_SMEM);

    k_down_rms<<<256, 192, 77888>>>(x, w_down, rms_w);
    k_qkv_mma<<<dim3(64, 72), 256, QKV_SMEM>>>(w_up);
    k_rope<<<dim3(8, 16, 64), 256>>>();
    k_attn_mma<<<dim3(32, 32), 256, ATT_SMEM>>>();
    k_out_mma<<<dim3(32, 8), 256>>>(w_o, out);
}

// round 9
// speedup vs baseline: 4.8611x; 1.2008x over previous
#include <cuda_runtime.h>
#include <cuda_fp16.h>
#include <math.h>

#define SS 2048
#define HH 16
#define DM 1024
#define DH 192
#define NQKV 9216
#define DL 3072
#define BHN 32
#define MROWS 4096

// Scratch (device globals: no allocation allowed)
__device__ float    g_h[MROWS * DH];              // 3 MB fp32
// Q in A-fragment tile layout: [bh][tile64(32)][12ks][4ms][128]  (u32 = half2)
__device__ unsigned g_qf[BHN * 32 * 6144];        // 25 MB
// K in B-fragment tile layout: [bh][tile64(32)][12ks][8ns][64]
__device__ unsigned g_kf[BHN * 32 * 6144];        // 25 MB
// V in B-fragment tile layout (k=j, n=d): [bh][tile64(32)][4ks][24ns][64]
__device__ unsigned g_vf[BHN * 32 * 6144];        // 25 MB
__device__ __half   g_attn[MROWS * DL];           // 25 MB, layout [b*S+s][h*192+d]

// ---------------------------------------------------------------------------
// f16 mma helpers (mma.sync m16n8k16, row.col, f32 accumulate)
//  A (16x16): (m,kp) -> [ks=k>>4][ms=m>>4][lane=(m&7)*4+(kp&3)][reg=((k&15)>=8)*2+((m&15)>=8)]
//  B (16x8):  (kp,n) -> [ks][ns=n>>3][lane=(n&7)*4+(kp&3)][reg=((k&15)>=8)]
//  Physical lane XOR-swizzled by slab: SW(lane, slab).
// ---------------------------------------------------------------------------
#define SW(l, s) ((l) ^ (((s) & 3) << 2))

__device__ __forceinline__ unsigned pack2(float a, float b) {
    __half2 h = __floats2half2_rn(a, b);
    return *(unsigned*)&h;
}

__device__ __forceinline__ void mma16(float4& d, const uint4& a, const uint2& b) {
    asm volatile("mma.sync.aligned.m16n8k16.row.col.f32.f16.f16.f32 "
                 "{%0,%1,%2,%3}, {%4,%5,%6,%7}, {%8,%9}, {%0,%1,%2,%3};\n"
                 : "+f"(d.x), "+f"(d.y), "+f"(d.z), "+f"(d.w)
                 : "r"(a.x), "r"(a.y), "r"(a.z), "r"(a.w), "r"(b.x), "r"(b.y));
}

__device__ __forceinline__ void cpa16(void* smem, const void* gmem) {
    unsigned sa = (unsigned)__cvta_generic_to_shared(smem);
    asm volatile("cp.async.cg.shared.global [%0], [%1], 16;" :: "r"(sa), "l"(gmem));
}
#define CP_COMMIT() asm volatile("cp.async.commit_group;")
#define CP_WAIT0()  asm volatile("cp.async.wait_group 0;")

// ---------------------------------------------------------------------------
// Kernel 1: h = rmsnorm(x @ w_down) * rms_w      [4096,1024]@[1024,192]
// ---------------------------------------------------------------------------
__global__ void k_down_rms(const float* __restrict__ x,
                           const float* __restrict__ w_down,
                           const float* __restrict__ rms_w) {
    extern __shared__ float sm[];
    float* xs  = sm;                  // 16*1024
    float* red = sm + 16 * 1024;      // 16*192
    float* rs  = red + 16 * 192;      // 16

    int t  = threadIdx.x;             // 0..191
    int m0 = blockIdx.x * 16;

    const float4* xin = (const float4*)(x + (size_t)m0 * DM);
    float4* xs4 = (float4*)xs;
    for (int i = t; i < 16 * DM / 4; i += 192) xs4[i] = xin[i];
    __syncthreads();

    float acc[16];
#pragma unroll
    for (int r = 0; r < 16; r++) acc[r] = 0.f;

    for (int k = 0; k < DM; k += 4) {
        float w0 = w_down[(k + 0) * DH + t];
        float w1 = w_down[(k + 1) * DH + t];
        float w2 = w_down[(k + 2) * DH + t];
        float w3 = w_down[(k + 3) * DH + t];
#pragma unroll
        for (int r = 0; r < 16; r++) {
            float4 xv = *(const float4*)&xs[r * DM + k];
            acc[r] += xv.x * w0 + xv.y * w1 + xv.z * w2 + xv.w * w3;
        }
    }

#pragma unroll
    for (int r = 0; r < 16; r++) red[r * 192 + t] = acc[r] * acc[r];
    __syncthreads();
    for (int st = 96; st >= 3; st >>= 1) {
        if (t < st) {
#pragma unroll
            for (int r = 0; r < 16; r++) red[r * 192 + t] += red[r * 192 + t + st];
        }
        __syncthreads();
    }
    if (t < 16) {
        float s3 = red[t * 192 + 0] + red[t * 192 + 1] + red[t * 192 + 2];
        rs[t] = rsqrtf(s3 / 192.0f + 1e-6f);
    }
    __syncthreads();

    float w = rms_w[t];
#pragma unroll
    for (int r = 0; r < 16; r++)
        g_h[(size_t)(m0 + r) * DH + t] = acc[r] * rs[r] * w;
}

// ---------------------------------------------------------------------------
// Kernel 2: qkv = h @ w_up (f16 mma). Q/K/V all written directly in
// fragment-tile layout. BM=64, BN=128, K=192. 8 warps 2(m) x 4(n).
// ---------------------------------------------------------------------------
#define QKV_SMEM ((12 * 4 * 128 + 12 * 16 * 64) * 4)   // 73728 B
__global__ void __launch_bounds__(256, 2) k_qkv_mma(const float* __restrict__ w_up) {
    extern __shared__ unsigned smu[];
    unsigned* Af = smu;                   // [12][4][128]
    unsigned* Bf = smu + 12 * 4 * 128;    // [12][16][64]

    int tid = threadIdx.x, lane = tid & 31, warp = tid >> 5;
    int wm = warp >> 2, wn = warp & 3;
    int m0 = blockIdx.x * 64;
    int n0 = blockIdx.y * 128;

    // A: 64x192 fp32 rows of g_h -> half2 pairs along k
    for (int i = tid; i < 64 * 48; i += 256) {
        int m = i / 48, k4 = (i % 48) * 4;
        float4 v = *(const float4*)&g_h[(size_t)(m0 + m) * DH + k4];
        int ks = k4 >> 4, ms = m >> 4;
        int reg = (((k4 & 15) >= 8) ? 2 : 0) + (((m & 15) >= 8) ? 1 : 0);
        int l0 = (m & 7) * 4 + ((k4 >> 1) & 3);
        unsigned* base = &Af[(ks * 4 + ms) * 128];
        base[SW(l0, ms) * 4 + reg]     = pack2(v.x, v.y);
        base[SW(l0 + 1, ms) * 4 + reg] = pack2(v.z, v.w);
    }
    // B: 192x128 fp32 rows of w_up -> pairs along k from two rows
    for (int i = tid; i < 96 * 32; i += 256) {
        int kp = i >> 5, n4 = (i & 31) * 4;
        int k = kp * 2;
        const float* p = &w_up[(size_t)k * NQKV + n0 + n4];
        float4 r0 = *(const float4*)p;
        float4 r1 = *(const float4*)(p + NQKV);
        int ks = k >> 4, reg = ((k & 15) >= 8) ? 1 : 0;
        int c = (k & 7) >> 1;
        float a0[4] = {r0.x, r0.y, r0.z, r0.w};
        float a1[4] = {r1.x, r1.y, r1.z, r1.w};
#pragma unroll
        for (int j = 0; j < 4; j++) {
            int n = n4 + j, ns = n >> 3;
            int l = (n & 7) * 4 + c;
            Bf[(ks * 16 + ns) * 64 + SW(l, ns) * 2 + reg] = pack2(a0[j], a1[j]);
        }
    }
    __syncthreads();

    float4 acc[2][4];
#pragma unroll
    for (int im = 0; im < 2; im++)
#pragma unroll
        for (int in = 0; in < 4; in++) acc[im][in] = make_float4(0.f, 0.f, 0.f, 0.f);

#pragma unroll
    for (int ks = 0; ks < 12; ks++) {
        uint4 a0 = *(const uint4*)&Af[(ks * 4 + wm * 2 + 0) * 128 + SW(lane, wm * 2) * 4];
        uint4 a1 = *(const uint4*)&Af[(ks * 4 + wm * 2 + 1) * 128 + SW(lane, wm * 2 + 1) * 4];
        uint2 b[4];
#pragma unroll
        for (int in = 0; in < 4; in++) {
            int ns = wn * 4 + in;
            b[in] = *(const uint2*)&Bf[(ks * 16 + ns) * 64 + SW(lane, ns) * 2];
        }
#pragma unroll
        for (int in = 0; in < 4; in++) { mma16(acc[0][in], a0, b[in]); mma16(acc[1][in], a1, b[in]); }
    }

    int b_ = m0 >> 11;
    int s0 = m0 & 2047;
    int ti = s0 >> 6;                        // 64-row tile index within bh
#pragma unroll
    for (int im = 0; im < 2; im++)
#pragma unroll
        for (int h = 0; h < 2; h++) {
            int m = wm * 32 + im * 16 + h * 8 + (lane >> 2);   // row in tile (0..63)
#pragma unroll
            for (int in2 = 0; in2 < 2; in2++)
#pragma unroll
                for (int cc = 0; cc < 2; cc++) {
                    float vlo, vhi;
                    if (h) { vlo = cc ? acc[im][in2].w : acc[im][in2].z;
                             vhi = cc ? acc[im][in2 + 2].w : acc[im][in2 + 2].z; }
                    else   { vlo = cc ? acc[im][in2].y : acc[im][in2].x;
                             vhi = cc ? acc[im][in2 + 2].y : acc[im][in2 + 2].x; }
                    int n = n0 + wn * 32 + in2 * 8 + 2 * (lane & 3) + cc;
                    int ten = n / 3072;
                    int l = n % 3072;
                    int h_ = l & 15, d = l >> 4;     // d even; pair (d, d+1)
                    int bh = b_ * HH + h_;
                    if (ten == 2) {
                        // V: B-frag (k=j sequence, n=d); halves stored individually
                        int j = m;
                        size_t base = (size_t)(bh * 32 + ti) * 6144;
                        int ksv = j >> 4;
                        int regv = ((j & 15) >= 8) ? 1 : 0;
                        int cv = (j >> 1) & 3;
                        int ns0 = d >> 3;
                        int lf0 = (d & 7) * 4 + cv;
                        __half* vh = (__half*)g_vf;
                        vh[(base + (ksv * 24 + ns0) * 64 + SW(lf0, ns0) * 2 + regv) * 2 + (j & 1)]
                            = __float2half(vlo);
                        vh[(base + (ksv * 24 + ns0) * 64 + SW(lf0 + 4, ns0) * 2 + regv) * 2 + (j & 1)]
                            = __float2half(vhi);
                    } else {
                        unsigned w = pack2(vlo, vhi);
                        int ks = d >> 4, c = (d & 7) >> 1;
                        int lf = (m & 7) * 4 + c;
                        if (ten == 0) {      // Q: A-frag
                            int ms = m >> 4;
                            int reg = (((d & 15) >= 8) ? 2 : 0) + (((m & 15) >= 8) ? 1 : 0);
                            g_qf[(size_t)(bh * 32 + ti) * 6144 +
                                 (ks * 4 + ms) * 128 + SW(lf, ms) * 4 + reg] = w;
                        } else {             // K: B-frag
                            int ns = m >> 3;
                            int reg = ((d & 15) >= 8) ? 1 : 0;
                            g_kf[(size_t)(bh * 32 + ti) * 6144 +
                                 (ks * 8 + ns) * 64 + SW(lf, ns) * 2 + reg] = w;
                        }
                    }
                }
        }
}

// ---------------------------------------------------------------------------
// Kernel 3: partial RoPE on q and k, editing fragment-layout words in place.
// ---------------------------------------------------------------------------
__global__ void k_rope() {
    int s = blockIdx.x * 256 + threadIdx.x;     // 0..2047
    int p = blockIdx.y;                         // 0..15
    int z = blockIdx.z;                         // 0..63: <32 q, else k
    int bh = z & 31;
    int d = 128 + 2 * p;

    float inv = (float)exp(-(double)(2 * p) / 32.0 * 9.210340371976184); // ln(10000)
    float ang = (float)s * inv;
    float c = cosf(ang), sn = sinf(ang);

    int ti = s >> 6, m = s & 63;
    int ks = d >> 4, cf = (d & 7) >> 1;
    int lf = (m & 7) * 4 + cf;
    unsigned* base;
    int idx;
    if (z < 32) {     // Q A-frag
        int ms = m >> 4;
        int reg = (((d & 15) >= 8) ? 2 : 0) + (((m & 15) >= 8) ? 1 : 0);
        base = g_qf + (size_t)(bh * 32 + ti) * 6144;
        idx = (ks * 4 + ms) * 128 + SW(lf, ms) * 4 + reg;
    } else {          // K B-frag
        int ns = m >> 3;
        int reg = ((d & 15) >= 8) ? 1 : 0;
        base = g_kf + (size_t)(bh * 32 + ti) * 6144;
        idx = (ks * 8 + ns) * 64 + SW(lf, ns) * 2 + reg;
    }
    unsigned u = base[idx];
    float2 xv = __half22float2(*(__half2*)&u);
    base[idx] = pack2(xv.x * c - xv.y * sn, xv.y * c + xv.x * sn);
}

// ---------------------------------------------------------------------------
// Kernel 4: causal flash attention. Q tile 128 rows, 512 threads (16 warps,
// 4m x 4n). K/V tiles double-buffered via cp.async; all fills raw 16B copies
// of fragment-layout gmem. SMEM ~166 KB, 1 CTA/SM, 4 warps/SMSP.
// ---------------------------------------------------------------------------
#define ATT_SMEM ((12288 * 3 + 4096 + 512 + 512 + 256 + 256) * 4)   // 169984 B
__global__ void __launch_bounds__(512, 1) k_attn_mma() {
    extern __shared__ unsigned smu[];
    unsigned* Qf = smu;                    // [2 half][12ks][4ms][128]
    unsigned* Kf = smu + 12288;            // 2 x [12ks][8ns][64]
    unsigned* Vf = smu + 24576;            // 2 x [4ks][24ns][64]
    unsigned* Pf = smu + 36864;            // [4ks][8ms][128]
    float* redm = (float*)(smu + 40960);   // [128][4]
    float* reds = redm + 512;              // [128][4]
    float* rowm = reds + 512;              // [2][128]
    float* rowl = rowm + 256;              // [2][128]

    int tid = threadIdx.x, lane = tid & 31, warp = tid >> 5;
    int wm = warp >> 2, wn = warp & 3;
    int bh = blockIdx.y;
    int it = 15 - blockIdx.x;              // longest tiles first
    int i0 = it * 128;

    // prefetch Q (two contiguous 64-row frag tiles = 3072 uint4) + K/V tile 0
    {
        const uint4* qt4 = (const uint4*)(g_qf + (size_t)(bh * 32 + it * 2) * 6144);
        const uint4* kt4 = (const uint4*)(g_kf + (size_t)(bh * 32) * 6144);
        const uint4* vt4 = (const uint4*)(g_vf + (size_t)(bh * 32) * 6144);
        uint4* Qd = (uint4*)Qf;
        uint4* Kd = (uint4*)Kf;
        uint4* Vd = (uint4*)Vf;
#pragma unroll
        for (int i = 0; i < 6; i++) cpa16(Qd + tid + i * 512, qt4 + tid + i * 512);
#pragma unroll
        for (int i = 0; i < 3; i++) {
            cpa16(Kd + tid + i * 512, kt4 + tid + i * 512);
            cpa16(Vd + tid + i * 512, vt4 + tid + i * 512);
        }
        CP_COMMIT();
    }
    if (tid < 128) { rowm[tid] = -3.0e38f; rowl[tid] = 0.f; }

    float4 o[2][6];
#pragma unroll
    for (int im = 0; im < 2; im++)
#pragma unroll
        for (int in = 0; in < 6; in++) o[im][in] = make_float4(0.f, 0.f, 0.f, 0.f);

    const float scale = 0.07216878364870323f;   // 1/sqrt(192)
    int ntile = 2 * it + 2;

    for (int jt = 0; jt < ntile; jt++) {
        int par = jt & 1;
        int kb = par * 6144;
        bool diag = (jt >= 2 * it);
        int off = jt * 64 - i0;

        CP_WAIT0();
        __syncthreads();                     // tile data ready; prev compute done

        // prefetch next K/V tile into other buffer (overlaps with compute)
        if (jt + 1 < ntile) {
            const uint4* kt4 = (const uint4*)(g_kf + (size_t)(bh * 32 + jt + 1) * 6144);
            const uint4* vt4 = (const uint4*)(g_vf + (size_t)(bh * 32 + jt + 1) * 6144);
            uint4* Kd = (uint4*)(Kf + (kb ^ 6144));
            uint4* Vd = (uint4*)(Vf + (kb ^ 6144));
#pragma unroll
            for (int i = 0; i < 3; i++) {
                cpa16(Kd + tid + i * 512, kt4 + tid + i * 512);
                cpa16(Vd + tid + i * 512, vt4 + tid + i * 512);
            }
        }
        CP_COMMIT();

        // S = Q K^T : warp tile 32(m) x 16(n)
        float4 s[2][2];
#pragma unroll
        for (int im = 0; im < 2; im++)
#pragma unroll
            for (int in = 0; in < 2; in++) s[im][in] = make_float4(0.f, 0.f, 0.f, 0.f);

#pragma unroll
        for (int ks = 0; ks < 12; ks++) {
            uint4 a[2];
#pragma unroll
            for (int im = 0; im < 2; im++) {
                int msg = wm * 2 + im;
                a[im] = *(const uint4*)&Qf[(msg >> 2) * 6144 +
                                           (ks * 4 + (msg & 3)) * 128 + SW(lane, msg & 3) * 4];
            }
            uint2 b0 = *(const uint2*)&Kf[kb + (ks * 8 + wn * 2 + 0) * 64 + SW(lane, wn * 2) * 2];
            uint2 b1 = *(const uint2*)&Kf[kb + (ks * 8 + wn * 2 + 1) * 64 + SW(lane, wn * 2 + 1) * 2];
            mma16(s[0][0], a[0], b0); mma16(s[0][1], a[0], b1);
            mma16(s[1][0], a[1], b0); mma16(s[1][1], a[1], b1);
        }

        // scale + mask in place; per-row tile max
        float mx[2][2];
#pragma unroll
        for (int im = 0; im < 2; im++) { mx[im][0] = -3.0e38f; mx[im][1] = -3.0e38f; }
#pragma unroll
        for (int im = 0; im < 2; im++)
#pragma unroll
            for (int in = 0; in < 2; in++) {
                float4& sv = s[im][in];
                sv.x *= scale; sv.y *= scale; sv.z *= scale; sv.w *= scale;
                if (diag) {
                    int colb = off + wn * 16 + in * 8 + 2 * (lane & 3);
                    int r0 = wm * 32 + im * 16 + (lane >> 2);
                    if (colb > r0)     sv.x = -1e9f;
                    if (colb + 1 > r0) sv.y = -1e9f;
                    if (colb > r0 + 8)     sv.z = -1e9f;
                    if (colb + 1 > r0 + 8) sv.w = -1e9f;
                }
                mx[im][0] = fmaxf(mx[im][0], fmaxf(sv.x, sv.y));
                mx[im][1] = fmaxf(mx[im][1], fmaxf(sv.z, sv.w));
            }
#pragma unroll
        for (int im = 0; im < 2; im++)
#pragma unroll
            for (int h = 0; h < 2; h++) {
                float m_ = mx[im][h];
                m_ = fmaxf(m_, __shfl_xor_sync(0xffffffffu, m_, 1));
                m_ = fmaxf(m_, __shfl_xor_sync(0xffffffffu, m_, 2));
                if ((lane & 3) == 0) {
                    int row = wm * 32 + im * 16 + h * 8 + (lane >> 2);
                    redm[row * 4 + wn] = m_;
                }
            }
        __syncthreads();

        // exp in place + partial sums + P -> A-frag; new row-max to next parity
        float cloc[2][2];
#pragma unroll
        for (int im = 0; im < 2; im++)
#pragma unroll
            for (int h = 0; h < 2; h++) {
                int row = wm * 32 + im * 16 + h * 8 + (lane >> 2);
                float4 rp = *(const float4*)&redm[row * 4];
                float mo = rowm[par * 128 + row];
                float mn = fmaxf(fmaxf(fmaxf(rp.x, rp.y), fmaxf(rp.z, rp.w)), mo);
                cloc[im][h] = __expf(mo - mn);
                float ssum = 0.f;
                int msg = wm * 2 + im;
#pragma unroll
                for (int in = 0; in < 2; in++) {
                    float v0 = h ? s[im][in].z : s[im][in].x;
                    float v1 = h ? s[im][in].w : s[im][in].y;
                    float e0 = __expf(v0 - mn);
                    float e1 = __expf(v1 - mn);
                    ssum += e0 + e1;
                    Pf[(wn * 8 + msg) * 128 + SW(lane, msg & 3) * 4 + (in * 2 + h)] = pack2(e0, e1);
                }
                ssum += __shfl_xor_sync(0xffffffffu, ssum, 1);
                ssum += __shfl_xor_sync(0xffffffffu, ssum, 2);
                if ((lane & 3) == 0) {
                    reds[row * 4 + wn] = ssum;
                    if (wn == 0) rowm[(par ^ 1) * 128 + row] = mn;
                }
            }
        __syncthreads();

        // distributed row-sum update, rescale O, then O += P @ V
        if (wn == 0 && (lane & 3) == 0) {
#pragma unroll
            for (int im = 0; im < 2; im++)
#pragma unroll
                for (int h = 0; h < 2; h++) {
                    int row = wm * 32 + im * 16 + h * 8 + (lane >> 2);
                    float4 sp = *(const float4*)&reds[row * 4];
                    float ts = sp.x + sp.y + sp.z + sp.w;
                    rowl[(par ^ 1) * 128 + row] = rowl[par * 128 + row] * cloc[im][h] + ts;
                }
        }
#pragma unroll
        for (int im = 0; im < 2; im++)
#pragma unroll
            for (int in = 0; in < 6; in++) {
                o[im][in].x *= cloc[im][0]; o[im][in].y *= cloc[im][0];
                o[im][in].z *= cloc[im][1]; o[im][in].w *= cloc[im][1];
            }
#pragma unroll
        for (int ksP = 0; ksP < 4; ksP++) {
            uint4 a[2];
#pragma unroll
            for (int im = 0; im < 2; im++) {
                int msg = wm * 2 + im;
                a[im] = *(const uint4*)&Pf[(ksP * 8 + msg) * 128 + SW(lane, msg & 3) * 4];
            }
            uint2 b[6];
#pragma unroll
            for (int in = 0; in < 6; in++) {
                int ns = wn * 6 + in;
                b[in] = *(const uint2*)&Vf[kb + (ksP * 24 + ns) * 64 + SW(lane, ns) * 2];
            }
#pragma unroll
            for (int in = 0; in < 6; in++) { mma16(o[0][in], a[0], b[in]); mma16(o[1][in], a[1], b[in]); }
        }
    }
    __syncthreads();                             // final rowl visible

    // epilogue: normalize, store half2 pairs to g_attn [b*S+s][h*192+d]
    int fpar = ntile & 1;
    int b_ = bh >> 4;
    int h_ = bh & 15;
#pragma unroll
    for (int im = 0; im < 2; im++)
#pragma unroll
        for (int h = 0; h < 2; h++) {
            int row = wm * 32 + im * 16 + h * 8 + (lane >> 2);
            float inv = 1.f / rowl[fpar * 128 + row];
            __half* dst = &g_attn[(size_t)(b_ * SS + i0 + row) * DL + h_ * DH];
#pragma unroll
            for (int in = 0; in < 6; in++) {
                int d = wn * 48 + in * 8 + 2 * (lane & 3);
                float vx = (h ? o[im][in].z : o[im][in].x) * inv;
                float vy = (h ? o[im][in].w : o[im][in].y) * inv;
                *(__half2*)&dst[d] = __floats2half2_rn(vx, vy);
            }
        }
}

// ---------------------------------------------------------------------------
// Kernel 5: out = g_attn @ w_o  (f16 mma)  [4096,3072]@[3072,1024]
// BM=128, BN=128, BK=64. 8 warps 4(m) x 2(n); warp 32x64.
// ---------------------------------------------------------------------------
__global__ void __launch_bounds__(256, 2) k_out_mma(const float* __restrict__ w_o,
                                                    float* __restrict__ out) {
    __shared__ unsigned Af[4 * 8 * 128];    // 16 KB
    __shared__ unsigned Bf[4 * 16 * 64];    // 16 KB

    int tid = threadIdx.x, lane = tid & 31, warp = tid >> 5;
    int wm = warp >> 1, wn = warp & 1;
    int m0 = blockIdx.x * 128;
    int n0 = blockIdx.y * 128;

    float4 acc[2][8];
#pragma unroll
    for (int im = 0; im < 2; im++)
#pragma unroll
        for (int in = 0; in < 8; in++) acc[im][in] = make_float4(0.f, 0.f, 0.f, 0.f);

    for (int kc = 0; kc < DL; kc += 64) {
        __syncthreads();
        // A: 128x64 halves of g_attn; k-pairs native
        for (int i = tid; i < 128 * 16; i += 256) {
            int m = i >> 4, k4 = (i & 15) * 4;
            uint2 v = *(const uint2*)&g_attn[(size_t)(m0 + m) * DL + kc + k4];
            int ks = k4 >> 4, ms = m >> 4;
            int reg = (((k4 & 15) >= 8) ? 2 : 0) + (((m & 15) >= 8) ? 1 : 0);
            int l0 = (m & 7) * 4 + ((k4 >> 1) & 3);
            unsigned* base = &Af[(ks * 8 + ms) * 128];
            base[SW(l0, ms) * 4 + reg]     = v.x;
            base[SW(l0 + 1, ms) * 4 + reg] = v.y;
        }
        // B: 64x128 fp32 rows of w_o; pairs along k from two rows
        for (int i = tid; i < 32 * 32; i += 256) {
            int kp = i >> 5, n4 = (i & 31) * 4;
            int k = kp * 2;
            const float* p = &w_o[(size_t)(kc + k) * DM + n0 + n4];
            float4 r0 = *(const float4*)p;
            float4 r1 = *(const float4*)(p + DM);
            int ks = k >> 4, reg = ((k & 15) >= 8) ? 1 : 0;
            int c = (k & 7) >> 1;
            float a0[4] = {r0.x, r0.y, r0.z, r0.w};
            float a1[4] = {r1.x, r1.y, r1.z, r1.w};
#pragma unroll
            for (int j = 0; j < 4; j++) {
                int n = n4 + j, ns = n >> 3;
                int l = (n & 7) * 4 + c;
                Bf[(ks * 16 + ns) * 64 + SW(l, ns) * 2 + reg] = pack2(a0[j], a1[j]);
            }
        }
        __syncthreads();

#pragma unroll
        for (int ks = 0; ks < 4; ks++) {
            uint4 a0 = *(const uint4*)&Af[(ks * 8 + wm * 2 + 0) * 128 + SW(lane, wm * 2) * 4];
            uint4 a1 = *(const uint4*)&Af[(ks * 8 + wm * 2 + 1) * 128 + SW(lane, wm * 2 + 1) * 4];
            uint2 b[8];
#pragma unroll
            for (int in = 0; in < 8; in++) {
                int ns = wn * 8 + in;
                b[in] = *(const uint2*)&Bf[(ks * 16 + ns) * 64 + SW(lane, ns) * 2];
            }
#pragma unroll
            for (int in = 0; in < 8; in++) { mma16(acc[0][in], a0, b[in]); mma16(acc[1][in], a1, b[in]); }
        }
    }

#pragma unroll
    for (int im = 0; im < 2; im++)
#pragma unroll
        for (int h = 0; h < 2; h++) {
            int m = m0 + wm * 32 + im * 16 + h * 8 + (lane >> 2);
#pragma unroll
            for (int in = 0; in < 8; in++) {
                int n = n0 + wn * 64 + in * 8 + 2 * (lane & 3);
                float2 v;
                v.x = h ? acc[im][in].z : acc[im][in].x;
                v.y = h ? acc[im][in].w : acc[im][in].y;
                *(float2*)&out[(size_t)m * DM + n] = v;
            }
        }
}

// ---------------------------------------------------------------------------
extern "C" void kernel_launch(void* const* d_in, const int* in_sizes, int n_in,
                              void* d_out, int out_size) {
    (void)in_sizes; (void)n_in; (void)out_size;
    const float* x      = (const float*)d_in[0];
    // d_in[1] = mask (int32 tril) — causality applied analytically, ignored
    const float* w_down = (const float*)d_in[2];
    const float* rms_w  = (const float*)d_in[3];
    const float* w_up   = (const float*)d_in[4];
    const float* w_o    = (const float*)d_in[5];
    float* out = (float*)d_out;

    cudaFuncSetAttribute(k_down_rms, cudaFuncAttributeMaxDynamicSharedMemorySize, 77888);
    cudaFuncSetAttribute(k_qkv_mma,  cudaFuncAttributeMaxDynamicSharedMemorySize, QKV_SMEM);
    cudaFuncSetAttribute(k_attn_mma, cudaFuncAttributeMaxDynamicSharedMemorySize, ATT_SMEM);

    k_down_rms<<<256, 192, 77888>>>(x, w_down, rms_w);
    k_qkv_mma<<<dim3(64, 72), 256, QKV_SMEM>>>(w_up);
    k_rope<<<dim3(8, 16, 64), 256>>>();
    k_attn_mma<<<dim3(16, 32), 512, ATT_SMEM>>>();
    k_out_mma<<<dim3(32, 8), 256>>>(w_o, out);
}

// round 10
// speedup vs baseline: 7.0357x; 1.4474x over previous
#include <cuda_runtime.h>
#include <cuda_fp16.h>
#include <math.h>

#define SS 2048
#define HH 16
#define DM 1024
#define DH 192
#define NQKV 9216
#define DL 3072
#define BHN 32
#define MROWS 4096

// Scratch (device globals: no allocation allowed)
__device__ __half   g_hh[MROWS * DH];             // 1.5 MB half
// Q in A-fragment tile layout: [bh][tile64(32)][12ks][4ms][128]  (u32 = half2)
__device__ unsigned g_qf[BHN * 32 * 6144];        // 25 MB
// K in B-fragment tile layout: [bh][tile64(32)][12ks][8ns][64]
__device__ unsigned g_kf[BHN * 32 * 6144];        // 25 MB
// V in B-fragment tile layout (k=j, n=d): [bh][tile64(32)][4ks][24ns][64]
__device__ unsigned g_vf[BHN * 32 * 6144];        // 25 MB
// O in A-fragment tile layout: [b(2)][mt(16)][kc(48)][4ks][8ms][128]
__device__ unsigned g_attnf[2 * 16 * 48 * 4096];  // 25 MB
// w_up prepacked half B-frag: [nb(72)][12ks][16ns][64]
__device__ unsigned g_wu[72 * 12288];             // 3.5 MB
// w_o prepacked half B-frag: [nb(8)][kc(48)][4ks][16ns][64]
__device__ unsigned g_wo[8 * 48 * 4096];          // 6.3 MB

// ---------------------------------------------------------------------------
// f16 mma helpers (mma.sync m16n8k16, row.col, f32 accumulate)
//  A (16x16): (m,kp) -> [ks=k>>4][ms=m>>4][lane=(m&7)*4+(kp&3)][reg=((k&15)>=8)*2+((m&15)>=8)]
//  B (16x8):  (kp,n) -> [ks][ns=n>>3][lane=(n&7)*4+(kp&3)][reg=((k&15)>=8)]
//  Physical lane XOR-swizzled by slab: SW(lane, slab).
// ---------------------------------------------------------------------------
#define SW(l, s) ((l) ^ (((s) & 3) << 2))

__device__ __forceinline__ unsigned pack2(float a, float b) {
    __half2 h = __floats2half2_rn(a, b);
    return *(unsigned*)&h;
}

__device__ __forceinline__ void mma16(float4& d, const uint4& a, const uint2& b) {
    asm volatile("mma.sync.aligned.m16n8k16.row.col.f32.f16.f16.f32 "
                 "{%0,%1,%2,%3}, {%4,%5,%6,%7}, {%8,%9}, {%0,%1,%2,%3};\n"
                 : "+f"(d.x), "+f"(d.y), "+f"(d.z), "+f"(d.w)
                 : "r"(a.x), "r"(a.y), "r"(a.z), "r"(a.w), "r"(b.x), "r"(b.y));
}

__device__ __forceinline__ void cpa16(void* smem, const void* gmem) {
    unsigned sa = (unsigned)__cvta_generic_to_shared(smem);
    asm volatile("cp.async.cg.shared.global [%0], [%1], 16;" :: "r"(sa), "l"(gmem));
}
#define CP_COMMIT() asm volatile("cp.async.commit_group;")
#define CP_WAIT0()  asm volatile("cp.async.wait_group 0;")

// ---------------------------------------------------------------------------
// Kernel 1: h = rmsnorm(x @ w_down) * rms_w   -> g_hh (half)
// ---------------------------------------------------------------------------
__global__ void k_down_rms(const float* __restrict__ x,
                           const float* __restrict__ w_down,
                           const float* __restrict__ rms_w) {
    extern __shared__ float sm[];
    float* xs  = sm;                  // 16*1024
    float* red = sm + 16 * 1024;      // 16*192
    float* rs  = red + 16 * 192;      // 16

    int t  = threadIdx.x;             // 0..191
    int m0 = blockIdx.x * 16;

    const float4* xin = (const float4*)(x + (size_t)m0 * DM);
    float4* xs4 = (float4*)xs;
    for (int i = t; i < 16 * DM / 4; i += 192) xs4[i] = xin[i];
    __syncthreads();

    float acc[16];
#pragma unroll
    for (int r = 0; r < 16; r++) acc[r] = 0.f;

    for (int k = 0; k < DM; k += 4) {
        float w0 = w_down[(k + 0) * DH + t];
        float w1 = w_down[(k + 1) * DH + t];
        float w2 = w_down[(k + 2) * DH + t];
        float w3 = w_down[(k + 3) * DH + t];
#pragma unroll
        for (int r = 0; r < 16; r++) {
            float4 xv = *(const float4*)&xs[r * DM + k];
            acc[r] += xv.x * w0 + xv.y * w1 + xv.z * w2 + xv.w * w3;
        }
    }

#pragma unroll
    for (int r = 0; r < 16; r++) red[r * 192 + t] = acc[r] * acc[r];
    __syncthreads();
    for (int st = 96; st >= 3; st >>= 1) {
        if (t < st) {
#pragma unroll
            for (int r = 0; r < 16; r++) red[r * 192 + t] += red[r * 192 + t + st];
        }
        __syncthreads();
    }
    if (t < 16) {
        float s3 = red[t * 192 + 0] + red[t * 192 + 1] + red[t * 192 + 2];
        rs[t] = rsqrtf(s3 / 192.0f + 1e-6f);
    }
    __syncthreads();

    float w = rms_w[t];
#pragma unroll
    for (int r = 0; r < 16; r++)
        g_hh[(size_t)(m0 + r) * DH + t] = __float2half(acc[r] * rs[r] * w);
}

// ---------------------------------------------------------------------------
// Prepack kernels: weights -> half B-fragment tile layout (run per launch)
// ---------------------------------------------------------------------------
__global__ void k_pack_wup(const float* __restrict__ w_up) {
    int idx = blockIdx.x * 256 + threadIdx.x;     // 96*9216
    if (idx >= 96 * NQKV) return;
    int kp = idx / NQKV, n = idx % NQKV;
    int k = kp * 2;
    float v0 = w_up[(size_t)k * NQKV + n];
    float v1 = w_up[(size_t)(k + 1) * NQKV + n];
    int nb = n >> 7, nn = n & 127;
    int ks = k >> 4, reg = ((k & 15) >= 8) ? 1 : 0, c = (k & 7) >> 1;
    int ns = nn >> 3, l = (nn & 7) * 4 + c;
    g_wu[(size_t)nb * 12288 + (ks * 16 + ns) * 64 + SW(l, ns) * 2 + reg] = pack2(v0, v1);
}

__global__ void k_pack_wo(const float* __restrict__ w_o) {
    int idx = blockIdx.x * 256 + threadIdx.x;     // 1536*1024
    if (idx >= 1536 * 1024) return;
    int kp = idx >> 10, n = idx & 1023;
    int k = kp * 2;
    float v0 = w_o[(size_t)k * DM + n];
    float v1 = w_o[(size_t)(k + 1) * DM + n];
    int kc = k >> 6, kk = k & 63;
    int ks = kk >> 4, reg = ((kk & 15) >= 8) ? 1 : 0, c = (kk & 7) >> 1;
    int nb = n >> 7, nn = n & 127;
    int ns = nn >> 3, l = (nn & 7) * 4 + c;
    g_wo[(size_t)(nb * 48 + kc) * 4096 + (ks * 16 + ns) * 64 + SW(l, ns) * 2 + reg]
        = pack2(v0, v1);
}

// ---------------------------------------------------------------------------
// Kernel 2: qkv = h @ w_up (f16 mma). BM=128, BN=128, K=192. 256 threads,
// 8 warps 2(m) x 4(n); warp 64x32. B tile = raw cp.async copy of g_wu.
// RoPE fused into the epilogue. Q/K/V written in fragment-tile layout.
// ---------------------------------------------------------------------------
#define QKV_SMEM ((12 * 8 * 128 + 12 * 16 * 64) * 4)   // 98304 B
__global__ void __launch_bounds__(256, 2) k_qkv_mma() {
    extern __shared__ unsigned smu[];
    unsigned* Af = smu;                   // [12][8][128]
    unsigned* Bf = smu + 12288;           // [12][16][64]

    int tid = threadIdx.x, lane = tid & 31, warp = tid >> 5;
    int wm = warp >> 2, wn = warp & 3;
    int m0 = blockIdx.x * 128;
    int nb = blockIdx.y;                  // 0..71

    // B: raw async copy of prepacked w_up block
    {
        const uint4* wsrc = (const uint4*)(g_wu + (size_t)nb * 12288);
        uint4* Bd = (uint4*)Bf;
#pragma unroll
        for (int i = 0; i < 12; i++) cpa16(Bd + tid + i * 256, wsrc + tid + i * 256);
        CP_COMMIT();
    }
    // A: 128x192 halves of g_hh -> A-frag (k-pairs native)
    for (int i = tid; i < 128 * 48; i += 256) {
        int m = i / 48, k4 = (i % 48) * 4;
        uint2 v = *(const uint2*)&g_hh[(size_t)(m0 + m) * DH + k4];
        int ks = k4 >> 4, ms = m >> 4;
        int reg = (((k4 & 15) >= 8) ? 2 : 0) + (((m & 15) >= 8) ? 1 : 0);
        int l0 = (m & 7) * 4 + ((k4 >> 1) & 3);
        unsigned* base = &Af[(ks * 8 + ms) * 128];
        base[SW(l0, ms) * 4 + reg]     = v.x;
        base[SW(l0 + 1, ms) * 4 + reg] = v.y;
    }
    CP_WAIT0();
    __syncthreads();

    float4 acc[4][4];
#pragma unroll
    for (int im = 0; im < 4; im++)
#pragma unroll
        for (int in = 0; in < 4; in++) acc[im][in] = make_float4(0.f, 0.f, 0.f, 0.f);

#pragma unroll
    for (int ks = 0; ks < 12; ks++) {
        uint4 a[4];
#pragma unroll
        for (int im = 0; im < 4; im++) {
            int ms = wm * 4 + im;
            a[im] = *(const uint4*)&Af[(ks * 8 + ms) * 128 + SW(lane, ms) * 4];
        }
        uint2 b[4];
#pragma unroll
        for (int in = 0; in < 4; in++) {
            int ns = wn * 4 + in;
            b[in] = *(const uint2*)&Bf[(ks * 16 + ns) * 64 + SW(lane, ns) * 2];
        }
#pragma unroll
        for (int im = 0; im < 4; im++)
#pragma unroll
            for (int in = 0; in < 4; in++) mma16(acc[im][in], a[im], b[in]);
    }

    int b_ = m0 >> 11;
    int s0 = m0 & 2047;
#pragma unroll
    for (int im = 0; im < 4; im++)
#pragma unroll
        for (int h = 0; h < 2; h++) {
            int m = wm * 64 + im * 16 + h * 8 + (lane >> 2);
            int s = s0 + m;
            int tile = s >> 6, mrow = s & 63;
#pragma unroll
            for (int in2 = 0; in2 < 2; in2++)
#pragma unroll
                for (int cc = 0; cc < 2; cc++) {
                    float vlo, vhi;
                    if (h) { vlo = cc ? acc[im][in2].w : acc[im][in2].z;
                             vhi = cc ? acc[im][in2 + 2].w : acc[im][in2 + 2].z; }
                    else   { vlo = cc ? acc[im][in2].y : acc[im][in2].x;
                             vhi = cc ? acc[im][in2 + 2].y : acc[im][in2 + 2].x; }
                    int n = nb * 128 + wn * 32 + in2 * 8 + 2 * (lane & 3) + cc;
                    int ten = n / 3072;
                    int l = n % 3072;
                    int h_ = l & 15, d = l >> 4;     // d even; pair (d, d+1)
                    int bh = b_ * HH + h_;
                    // fused partial RoPE on q/k for d in [128,160)
                    if (ten != 2 && (unsigned)(d - 128) < 32u) {
                        int p = (d - 128) >> 1;
                        float inv = exp2f(-(float)p * 0.8304820237218406f); // log2(1e4)/16
                        float ang = (float)s * inv;
                        float sn, cs;
                        sincosf(ang, &sn, &cs);
                        float t0 = vlo * cs - vhi * sn;
                        vhi = vhi * cs + vlo * sn;
                        vlo = t0;
                    }
                    if (ten == 2) {
                        // V: B-frag (k=j sequence, n=d); halves stored individually
                        int j = mrow;
                        size_t base = (size_t)(bh * 32 + tile) * 6144;
                        int ksv = j >> 4;
                        int regv = ((j & 15) >= 8) ? 1 : 0;
                        int cv = (j >> 1) & 3;
                        int ns0 = d >> 3;
                        int lf0 = (d & 7) * 4 + cv;
                        __half* vh = (__half*)g_vf;
                        vh[(base + (ksv * 24 + ns0) * 64 + SW(lf0, ns0) * 2 + regv) * 2 + (j & 1)]
                            = __float2half(vlo);
                        vh[(base + (ksv * 24 + ns0) * 64 + SW(lf0 + 4, ns0) * 2 + regv) * 2 + (j & 1)]
                            = __float2half(vhi);
                    } else {
                        unsigned w = pack2(vlo, vhi);
                        int ks = d >> 4, c = (d & 7) >> 1;
                        int lf = (mrow & 7) * 4 + c;
                        if (ten == 0) {      // Q: A-frag
                            int ms = mrow >> 4;
                            int reg = (((d & 15) >= 8) ? 2 : 0) + (((mrow & 15) >= 8) ? 1 : 0);
                            g_qf[(size_t)(bh * 32 + tile) * 6144 +
                                 (ks * 4 + ms) * 128 + SW(lf, ms) * 4 + reg] = w;
                        } else {             // K: B-frag
                            int ns = mrow >> 3;
                            int reg = ((d & 15) >= 8) ? 1 : 0;
                            g_kf[(size_t)(bh * 32 + tile) * 6144 +
                                 (ks * 8 + ns) * 64 + SW(lf, ns) * 2 + reg] = w;
                        }
                    }
                }
        }
}

// ---------------------------------------------------------------------------
// Kernel 4: causal flash attention. Q tile 128 rows, 512 threads (16 warps,
// 4m x 4n). K/V double-buffered cp.async raw copies. Epilogue writes O in
// A-fragment tile layout (g_attnf).
// ---------------------------------------------------------------------------
#define ATT_SMEM ((12288 * 3 + 4096 + 512 + 512 + 256 + 256) * 4)   // 169984 B
__global__ void __launch_bounds__(512, 1) k_attn_mma() {
    extern __shared__ unsigned smu[];
    unsigned* Qf = smu;                    // [2 half][12ks][4ms][128]
    unsigned* Kf = smu + 12288;            // 2 x [12ks][8ns][64]
    unsigned* Vf = smu + 24576;            // 2 x [4ks][24ns][64]
    unsigned* Pf = smu + 36864;            // [4ks][8ms][128]
    float* redm = (float*)(smu + 40960);   // [128][4]
    float* reds = redm + 512;              // [128][4]
    float* rowm = reds + 512;              // [2][128]
    float* rowl = rowm + 256;              // [2][128]

    int tid = threadIdx.x, lane = tid & 31, warp = tid >> 5;
    int wm = warp >> 2, wn = warp & 3;
    int bh = blockIdx.y;
    int it = 15 - blockIdx.x;              // longest tiles first
    int i0 = it * 128;

    // prefetch Q (two contiguous 64-row frag tiles = 3072 uint4) + K/V tile 0
    {
        const uint4* qt4 = (const uint4*)(g_qf + (size_t)(bh * 32 + it * 2) * 6144);
        const uint4* kt4 = (const uint4*)(g_kf + (size_t)(bh * 32) * 6144);
        const uint4* vt4 = (const uint4*)(g_vf + (size_t)(bh * 32) * 6144);
        uint4* Qd = (uint4*)Qf;
        uint4* Kd = (uint4*)Kf;
        uint4* Vd = (uint4*)Vf;
#pragma unroll
        for (int i = 0; i < 6; i++) cpa16(Qd + tid + i * 512, qt4 + tid + i * 512);
#pragma unroll
        for (int i = 0; i < 3; i++) {
            cpa16(Kd + tid + i * 512, kt4 + tid + i * 512);
            cpa16(Vd + tid + i * 512, vt4 + tid + i * 512);
        }
        CP_COMMIT();
    }
    if (tid < 128) { rowm[tid] = -3.0e38f; rowl[tid] = 0.f; }

    float4 o[2][6];
#pragma unroll
    for (int im = 0; im < 2; im++)
#pragma unroll
        for (int in = 0; in < 6; in++) o[im][in] = make_float4(0.f, 0.f, 0.f, 0.f);

    const float scale = 0.07216878364870323f;   // 1/sqrt(192)
    int ntile = 2 * it + 2;

    for (int jt = 0; jt < ntile; jt++) {
        int par = jt & 1;
        int kb = par * 6144;
        bool diag = (jt >= 2 * it);
        int off = jt * 64 - i0;

        CP_WAIT0();
        __syncthreads();                     // tile data ready; prev compute done

        // prefetch next K/V tile into other buffer (overlaps with compute)
        if (jt + 1 < ntile) {
            const uint4* kt4 = (const uint4*)(g_kf + (size_t)(bh * 32 + jt + 1) * 6144);
            const uint4* vt4 = (const uint4*)(g_vf + (size_t)(bh * 32 + jt + 1) * 6144);
            uint4* Kd = (uint4*)(Kf + (kb ^ 6144));
            uint4* Vd = (uint4*)(Vf + (kb ^ 6144));
#pragma unroll
            for (int i = 0; i < 3; i++) {
                cpa16(Kd + tid + i * 512, kt4 + tid + i * 512);
                cpa16(Vd + tid + i * 512, vt4 + tid + i * 512);
            }
        }
        CP_COMMIT();

        // S = Q K^T : warp tile 32(m) x 16(n)
        float4 s[2][2];
#pragma unroll
        for (int im = 0; im < 2; im++)
#pragma unroll
            for (int in = 0; in < 2; in++) s[im][in] = make_float4(0.f, 0.f, 0.f, 0.f);

#pragma unroll
        for (int ks = 0; ks < 12; ks++) {
            uint4 a[2];
#pragma unroll
            for (int im = 0; im < 2; im++) {
                int msg = wm * 2 + im;
                a[im] = *(const uint4*)&Qf[(msg >> 2) * 6144 +
                                           (ks * 4 + (msg & 3)) * 128 + SW(lane, msg & 3) * 4];
            }
            uint2 b0 = *(const uint2*)&Kf[kb + (ks * 8 + wn * 2 + 0) * 64 + SW(lane, wn * 2) * 2];
            uint2 b1 = *(const uint2*)&Kf[kb + (ks * 8 + wn * 2 + 1) * 64 + SW(lane, wn * 2 + 1) * 2];
            mma16(s[0][0], a[0], b0); mma16(s[0][1], a[0], b1);
            mma16(s[1][0], a[1], b0); mma16(s[1][1], a[1], b1);
        }

        // scale + mask in place; per-row tile max
        float mx[2][2];
#pragma unroll
        for (int im = 0; im < 2; im++) { mx[im][0] = -3.0e38f; mx[im][1] = -3.0e38f; }
#pragma unroll
        for (int im = 0; im < 2; im++)
#pragma unroll
            for (int in = 0; in < 2; in++) {
                float4& sv = s[im][in];
                sv.x *= scale; sv.y *= scale; sv.z *= scale; sv.w *= scale;
                if (diag) {
                    int colb = off + wn * 16 + in * 8 + 2 * (lane & 3);
                    int r0 = wm * 32 + im * 16 + (lane >> 2);
                    if (colb > r0)     sv.x = -1e9f;
                    if (colb + 1 > r0) sv.y = -1e9f;
                    if (colb > r0 + 8)     sv.z = -1e9f;
                    if (colb + 1 > r0 + 8) sv.w = -1e9f;
                }
                mx[im][0] = fmaxf(mx[im][0], fmaxf(sv.x, sv.y));
                mx[im][1] = fmaxf(mx[im][1], fmaxf(sv.z, sv.w));
            }
#pragma unroll
        for (int im = 0; im < 2; im++)
#pragma unroll
            for (int h = 0; h < 2; h++) {
                float m_ = mx[im][h];
                m_ = fmaxf(m_, __shfl_xor_sync(0xffffffffu, m_, 1));
                m_ = fmaxf(m_, __shfl_xor_sync(0xffffffffu, m_, 2));
                if ((lane & 3) == 0) {
                    int row = wm * 32 + im * 16 + h * 8 + (lane >> 2);
                    redm[row * 4 + wn] = m_;
                }
            }
        __syncthreads();

        // exp in place + partial sums + P -> A-frag; new row-max to next parity
        float cloc[2][2];
#pragma unroll
        for (int im = 0; im < 2; im++)
#pragma unroll
            for (int h = 0; h < 2; h++) {
                int row = wm * 32 + im * 16 + h * 8 + (lane >> 2);
                float4 rp = *(const float4*)&redm[row * 4];
                float mo = rowm[par * 128 + row];
                float mn = fmaxf(fmaxf(fmaxf(rp.x, rp.y), fmaxf(rp.z, rp.w)), mo);
                cloc[im][h] = __expf(mo - mn);
                float ssum = 0.f;
                int msg = wm * 2 + im;
#pragma unroll
                for (int in = 0; in < 2; in++) {
                    float v0 = h ? s[im][in].z : s[im][in].x;
                    float v1 = h ? s[im][in].w : s[im][in].y;
                    float e0 = __expf(v0 - mn);
                    float e1 = __expf(v1 - mn);
                    ssum += e0 + e1;
                    Pf[(wn * 8 + msg) * 128 + SW(lane, msg & 3) * 4 + (in * 2 + h)] = pack2(e0, e1);
                }
                ssum += __shfl_xor_sync(0xffffffffu, ssum, 1);
                ssum += __shfl_xor_sync(0xffffffffu, ssum, 2);
                if ((lane & 3) == 0) {
                    reds[row * 4 + wn] = ssum;
                    if (wn == 0) rowm[(par ^ 1) * 128 + row] = mn;
                }
            }
        __syncthreads();

        // distributed row-sum update, rescale O, then O += P @ V
        if (wn == 0 && (lane & 3) == 0) {
#pragma unroll
            for (int im = 0; im < 2; im++)
#pragma unroll
                for (int h = 0; h < 2; h++) {
                    int row = wm * 32 + im * 16 + h * 8 + (lane >> 2);
                    float4 sp = *(const float4*)&reds[row * 4];
                    float ts = sp.x + sp.y + sp.z + sp.w;
                    rowl[(par ^ 1) * 128 + row] = rowl[par * 128 + row] * cloc[im][h] + ts;
                }
        }
#pragma unroll
        for (int im = 0; im < 2; im++)
#pragma unroll
            for (int in = 0; in < 6; in++) {
                o[im][in].x *= cloc[im][0]; o[im][in].y *= cloc[im][0];
                o[im][in].z *= cloc[im][1]; o[im][in].w *= cloc[im][1];
            }
#pragma unroll
        for (int ksP = 0; ksP < 4; ksP++) {
            uint4 a[2];
#pragma unroll
            for (int im = 0; im < 2; im++) {
                int msg = wm * 2 + im;
                a[im] = *(const uint4*)&Pf[(ksP * 8 + msg) * 128 + SW(lane, msg & 3) * 4];
            }
            uint2 b[6];
#pragma unroll
            for (int in = 0; in < 6; in++) {
                int ns = wn * 6 + in;
                b[in] = *(const uint2*)&Vf[kb + (ksP * 24 + ns) * 64 + SW(lane, ns) * 2];
            }
#pragma unroll
            for (int in = 0; in < 6; in++) { mma16(o[0][in], a[0], b[in]); mma16(o[1][in], a[1], b[in]); }
        }
    }
    __syncthreads();                             // final rowl visible

    // epilogue: normalize, write O in A-frag tile layout (g_attnf)
    int fpar = ntile & 1;
    int b_ = bh >> 4;
    int h_ = bh & 15;
    size_t tb = (size_t)(b_ * 16 + it) * 48 * 4096;
#pragma unroll
    for (int im = 0; im < 2; im++)
#pragma unroll
        for (int h = 0; h < 2; h++) {
            int row = wm * 32 + im * 16 + h * 8 + (lane >> 2);
            float inv = 1.f / rowl[fpar * 128 + row];
            int ms = row >> 4;
            int regm = ((row & 15) >= 8) ? 1 : 0;
#pragma unroll
            for (int in = 0; in < 6; in++) {
                int d = wn * 48 + in * 8 + 2 * (lane & 3);
                int l = h_ * 192 + d;
                int kc = l >> 6, kk = l & 63;
                int ks = kk >> 4;
                int regk = ((kk & 15) >= 8) ? 2 : 0;
                int c = (kk >> 1) & 3;
                int lw = (row & 7) * 4 + c;
                float vx = (h ? o[im][in].z : o[im][in].x) * inv;
                float vy = (h ? o[im][in].w : o[im][in].y) * inv;
                g_attnf[tb + ((kc * 4 + ks) * 8 + ms) * 128 + SW(lw, ms) * 4 + (regk + regm)]
                    = pack2(vx, vy);
            }
        }
}

// ---------------------------------------------------------------------------
// Kernel 5: out = O @ w_o  (f16 mma)  [4096,3072]@[3072,1024]
// BM=128, BN=128, BK=64, 48 chunks, double-buffered cp.async raw copies
// (A from g_attnf frag tiles, B from g_wo prepack). 8 warps 4m x 2n.
// ---------------------------------------------------------------------------
#define OUT_SMEM (2 * (4096 + 4096) * 4)   // 65536 B
__global__ void __launch_bounds__(256, 2) k_out_mma(float* __restrict__ out) {
    extern __shared__ unsigned smu[];
    unsigned* Af = smu;          // 2 x [4ks][8ms][128]
    unsigned* Bf = smu + 8192;   // 2 x [4ks][16ns][64]

    int tid = threadIdx.x, lane = tid & 31, warp = tid >> 5;
    int wm = warp >> 1, wn = warp & 1;
    int m0 = blockIdx.x * 128;
    int b_ = m0 >> 11, mt = (m0 >> 7) & 15;
    int nb = blockIdx.y;
    int n0 = nb * 128;

    const uint4* asrc = (const uint4*)(g_attnf + (size_t)(b_ * 16 + mt) * 48 * 4096);
    const uint4* bsrc = (const uint4*)(g_wo + (size_t)nb * 48 * 4096);

    {
        uint4* Ad = (uint4*)Af;
        uint4* Bd = (uint4*)Bf;
#pragma unroll
        for (int i = 0; i < 4; i++) {
            cpa16(Ad + tid + i * 256, asrc + tid + i * 256);
            cpa16(Bd + tid + i * 256, bsrc + tid + i * 256);
        }
        CP_COMMIT();
    }

    float4 acc[2][8];
#pragma unroll
    for (int im = 0; im < 2; im++)
#pragma unroll
        for (int in = 0; in < 8; in++) acc[im][in] = make_float4(0.f, 0.f, 0.f, 0.f);

    for (int kc = 0; kc < 48; kc++) {
        int boff = (kc & 1) * 4096;
        CP_WAIT0();
        __syncthreads();

        if (kc + 1 < 48) {
            int nboff = ((kc + 1) & 1) * 1024;
            uint4* Ad = (uint4*)Af + nboff;
            uint4* Bd = (uint4*)Bf + nboff;
            const uint4* an = asrc + (kc + 1) * 1024;
            const uint4* bn = bsrc + (kc + 1) * 1024;
#pragma unroll
            for (int i = 0; i < 4; i++) {
                cpa16(Ad + tid + i * 256, an + tid + i * 256);
                cpa16(Bd + tid + i * 256, bn + tid + i * 256);
            }
        }
        CP_COMMIT();

#pragma unroll
        for (int ks = 0; ks < 4; ks++) {
            uint4 a0 = *(const uint4*)&Af[boff + (ks * 8 + wm * 2 + 0) * 128 + SW(lane, wm * 2) * 4];
            uint4 a1 = *(const uint4*)&Af[boff + (ks * 8 + wm * 2 + 1) * 128 + SW(lane, wm * 2 + 1) * 4];
            uint2 b[8];
#pragma unroll
            for (int in = 0; in < 8; in++) {
                int ns = wn * 8 + in;
                b[in] = *(const uint2*)&Bf[boff + (ks * 16 + ns) * 64 + SW(lane, ns) * 2];
            }
#pragma unroll
            for (int in = 0; in < 8; in++) { mma16(acc[0][in], a0, b[in]); mma16(acc[1][in], a1, b[in]); }
        }
    }

#pragma unroll
    for (int im = 0; im < 2; im++)
#pragma unroll
        for (int h = 0; h < 2; h++) {
            int m = m0 + wm * 32 + im * 16 + h * 8 + (lane >> 2);
#pragma unroll
            for (int in = 0; in < 8; in++) {
                int n = n0 + wn * 64 + in * 8 + 2 * (lane & 3);
                float2 v;
                v.x = h ? acc[im][in].z : acc[im][in].x;
                v.y = h ? acc[im][in].w : acc[im][in].y;
                *(float2*)&out[(size_t)m * DM + n] = v;
            }
        }
}

// ---------------------------------------------------------------------------
extern "C" void kernel_launch(void* const* d_in, const int* in_sizes, int n_in,
                              void* d_out, int out_size) {
    (void)in_sizes; (void)n_in; (void)out_size;
    const float* x      = (const float*)d_in[0];
    // d_in[1] = mask (int32 tril) — causality applied analytically, ignored
    const float* w_down = (const float*)d_in[2];
    const float* rms_w  = (const float*)d_in[3];
    const float* w_up   = (const float*)d_in[4];
    const float* w_o    = (const float*)d_in[5];
    float* out = (float*)d_out;

    cudaFuncSetAttribute(k_down_rms, cudaFuncAttributeMaxDynamicSharedMemorySize, 77888);
    cudaFuncSetAttribute(k_qkv_mma,  cudaFuncAttributeMaxDynamicSharedMemorySize, QKV_SMEM);
    cudaFuncSetAttribute(k_attn_mma, cudaFuncAttributeMaxDynamicSharedMemorySize, ATT_SMEM);
    cudaFuncSetAttribute(k_out_mma,  cudaFuncAttributeMaxDynamicSharedMemorySize, OUT_SMEM);

    k_down_rms<<<256, 192, 77888>>>(x, w_down, rms_w);
    k_pack_wup<<<(96 * NQKV + 255) / 256, 256>>>(w_up);
    k_pack_wo<<<(1536 * 1024 + 255) / 256, 256>>>(w_o);
    k_qkv_mma<<<dim3(32, 72), 256, QKV_SMEM>>>();
    k_attn_mma<<<dim3(16, 32), 512, ATT_SMEM>>>();
    k_out_mma<<<dim3(32, 8), 256, OUT_SMEM>>>(out);
}